// round 7
// baseline (speedup 1.0000x reference)
#include <cuda_runtime.h>

// MaskedCommonWeightSimpleLinearGNN:
//   w = LW * A (binary mask ~1%, 8192x8192), same w for all 3 layers.
//   out = (w^3 x) M + (w^2 1) c0^T + (w 1) c1^T + 1 b2^T
//     M = W0^T W1^T W2^T, c0 = W2 W1 b0, c1 = W2 b1
// Pipeline (4 launches):
//   build  : scan A -> cols in SMEM -> gather LW (vals, s1) -> FUSED layer-1
//            SpMM (y1 = w x, x-gathers hide under other warps' A streaming)
//   prep   : M, c0, c1
//   spmm x2: layer2 (+strided s2 = w s1), layer3 (fused M + rank-1 epilogue)

#define NN   8192
#define DD   64
#define CAP  160      // Binomial(8192,0.01): mean 82, sigma 9 -> mean+8.7sigma
#define RPB  16

// ---- allocation-free scratch ----
__device__ unsigned short g_cols[(size_t)NN * CAP];
__device__ float          g_vals[(size_t)NN * CAP];
__device__ int            g_cnt[NN];
__device__ float          g_s1[NN];
__device__ float          g_s2[NN];
__device__ float          g_M[DD * DD];
__device__ float          g_c0[DD];
__device__ float          g_c1[DD];
__device__ float          g_buf0[(size_t)NN * DD];
__device__ float          g_buf1[(size_t)NN * DD];

// ============================================================================
// 1) build + fused layer-1. One warp per row:
//    a) stream A (float4, prefetch depth 1), ballot-compact cols into SMEM
//    b) gather LW at nonzeros -> vals (SMEM + global), s1 row sum
//    c) y1[row,:] = sum_k v_k * x[c_k,:]  -- half-warp per k-parity,
//       16 lanes x float4 across 64 features, unroll-4 (8 gathers/warp in flight)
// ============================================================================
__global__ void __launch_bounds__(256)
build_kernel(const float* __restrict__ A, const float* __restrict__ LW,
             const float* __restrict__ x, float* __restrict__ y1) {
    __shared__ unsigned short sCols[8][CAP];
    __shared__ float          sVals[8][CAP];

    int wid  = threadIdx.x >> 5;
    int lane = threadIdx.x & 31;
    int row  = blockIdx.x * 8 + wid;

    const float4* a4 = reinterpret_cast<const float4*>(A + (size_t)row * NN);
    unsigned short* wc = sCols[wid];
    float*          wv = sVals[wid];
    unsigned lt = (1u << lane) - 1u;

    // --- a) scan ---
    int cnt = 0;
    float4 cur = a4[lane];
    for (int c = 0; c < NN / 128; ++c) {
        float4 nxt;
        if (c + 1 < NN / 128) nxt = a4[(c + 1) * 32 + lane];

        float a[4] = {cur.x, cur.y, cur.z, cur.w};
        int cb = c * 128 + lane * 4;
        #pragma unroll
        for (int r = 0; r < 4; ++r) {
            bool nz = (a[r] != 0.0f);
            unsigned m = __ballot_sync(0xffffffffu, nz);
            if (nz) {
                int pos = cnt + __popc(m & lt);
                if (pos < CAP) wc[pos] = (unsigned short)(cb + r);
            }
            cnt += __popc(m);
        }
        cur = nxt;
    }
    if (cnt > CAP) cnt = CAP;
    __syncwarp();

    // --- b) gather LW ---
    const float* lw = LW + (size_t)row * NN;
    unsigned short* gcols = g_cols + (size_t)row * CAP;
    float*          gvals = g_vals + (size_t)row * CAP;

    float s = 0.0f;
    #pragma unroll
    for (int j = 0; j < CAP / 32; ++j) {
        int k = j * 32 + lane;
        if (k < cnt) {
            unsigned short c = wc[k];
            float v = __ldg(&lw[c]);
            gvals[k] = v;
            gcols[k] = c;
            wv[k]    = v;
            s += v;
        }
    }
    #pragma unroll
    for (int o = 16; o; o >>= 1) s += __shfl_xor_sync(0xffffffffu, s, o);
    if (lane == 0) {
        g_cnt[row] = cnt;
        g_s1[row]  = s;
    }
    __syncwarp();

    // --- c) fused layer-1 SpMM: y1[row] = sum v_k x[c_k,:] ---
    const float4* x4 = reinterpret_cast<const float4*>(x);
    int half = lane >> 4;        // k parity
    int l4   = lane & 15;        // feature quad

    float4 a0 = make_float4(0.f,0.f,0.f,0.f), a1 = a0, a2 = a0, a3 = a0;
    int k = half;
    for (; k + 6 < cnt; k += 8) {
        int   c0 = wc[k],   c1 = wc[k+2], c2 = wc[k+4], c3 = wc[k+6];
        float v0 = wv[k],   v1 = wv[k+2], v2 = wv[k+4], v3 = wv[k+6];
        float4 g0 = __ldg(&x4[c0 * 16 + l4]);
        float4 g1 = __ldg(&x4[c1 * 16 + l4]);
        float4 g2 = __ldg(&x4[c2 * 16 + l4]);
        float4 g3 = __ldg(&x4[c3 * 16 + l4]);
        a0.x += v0*g0.x; a0.y += v0*g0.y; a0.z += v0*g0.z; a0.w += v0*g0.w;
        a1.x += v1*g1.x; a1.y += v1*g1.y; a1.z += v1*g1.z; a1.w += v1*g1.w;
        a2.x += v2*g2.x; a2.y += v2*g2.y; a2.z += v2*g2.z; a2.w += v2*g2.w;
        a3.x += v3*g3.x; a3.y += v3*g3.y; a3.z += v3*g3.z; a3.w += v3*g3.w;
    }
    for (; k < cnt; k += 2) {
        int c = wc[k]; float v = wv[k];
        float4 g = __ldg(&x4[c * 16 + l4]);
        a0.x += v*g.x; a0.y += v*g.y; a0.z += v*g.z; a0.w += v*g.w;
    }
    float4 acc;
    acc.x = (a0.x + a1.x) + (a2.x + a3.x);
    acc.y = (a0.y + a1.y) + (a2.y + a3.y);
    acc.z = (a0.z + a1.z) + (a2.z + a3.z);
    acc.w = (a0.w + a1.w) + (a2.w + a3.w);
    // combine the two k-parity halves (lane <-> lane^16)
    acc.x += __shfl_xor_sync(0xffffffffu, acc.x, 16);
    acc.y += __shfl_xor_sync(0xffffffffu, acc.y, 16);
    acc.z += __shfl_xor_sync(0xffffffffu, acc.z, 16);
    acc.w += __shfl_xor_sync(0xffffffffu, acc.w, 16);
    if (half == 0)
        reinterpret_cast<float4*>(y1)[(size_t)row * 16 + l4] = acc;
}

// ============================================================================
// 2) prep: M = W0^T W1^T W2^T, c0 = W2 W1 b0, c1 = W2 b1.
//    16 blocks x 256 threads; padded shared (stride 65) -> conflict-free.
// ============================================================================
__global__ void __launch_bounds__(256)
prep_kernel(const float* __restrict__ W0, const float* __restrict__ W1,
            const float* __restrict__ b0, const float* __restrict__ W2,
            const float* __restrict__ b1) {
    __shared__ float sW0[DD * DD];        // [f*64+d], d const per warp -> broadcast
    __shared__ float sW1[DD * 65];
    __shared__ float sW2[DD * 65];
    __shared__ float sP[4 * 65];
    __shared__ float sQ[DD];

    int tid = threadIdx.x;
    for (int i = tid; i < DD * DD; i += 256) {
        sW0[i] = W0[i];
        sW1[(i >> 6) * 65 + (i & 63)] = W1[i];
        sW2[(i >> 6) * 65 + (i & 63)] = W2[i];
    }
    __syncthreads();

    int dl = tid >> 6;
    int e  = tid & 63;
    int d  = blockIdx.x * 4 + dl;

    float p = 0.0f;
    #pragma unroll
    for (int f = 0; f < DD; ++f) p += sW0[f * DD + d] * sW1[e * 65 + f];
    sP[dl * 65 + e] = p;

    if (blockIdx.x == 0 && tid < DD) {
        float s = 0.0f;
        #pragma unroll
        for (int f = 0; f < DD; ++f) s += sW1[tid * 65 + f] * __ldg(&b0[f]);
        sQ[tid] = s;
    }
    __syncthreads();

    int t = e;
    float msum = 0.0f;
    #pragma unroll
    for (int ee = 0; ee < DD; ++ee) msum += sP[dl * 65 + ee] * sW2[t * 65 + ee];
    g_M[d * DD + t] = msum;

    if (blockIdx.x == 0 && tid < DD) {
        float s0 = 0.0f, s1v = 0.0f;
        #pragma unroll
        for (int ee = 0; ee < DD; ++ee) {
            float w2 = sW2[tid * 65 + ee];
            s0  += w2 * sQ[ee];
            s1v += w2 * __ldg(&b1[ee]);
        }
        g_c0[tid] = s0;
        g_c1[tid] = s1v;
    }
}

// ============================================================================
// 3) SpMM template. 16 rows/block, 256 threads (16 lanes/row).
//    cols (ushort) + vals staged in shared; 8-way unrolled float4 gathers.
//    S2: strided post-loop computing s2 = w s1.
//    FINAL: fused epilogue out = y M + s2 c0^T + s1 c1^T + b2.
// ============================================================================
template <bool S2, bool FINAL>
__global__ void __launch_bounds__(256)
spmm_kernel(const float* __restrict__ xin, float* __restrict__ xout,
            const float* __restrict__ b2) {
    __shared__ unsigned short sC[RPB * CAP];     // 5 KB
    __shared__ float          sV[RPB * CAP];     // 10 KB
    __shared__ int            sCnt[RPB];
    __shared__ float          sM[FINAL ? DD * DD : 1];
    __shared__ float          shY[FINAL ? RPB : 1][DD];

    int tid  = threadIdx.x;
    int row0 = blockIdx.x * RPB;

    if (tid < RPB) sCnt[tid] = g_cnt[row0 + tid];

    {
        const uint2* gc2 = reinterpret_cast<const uint2*>(g_cols + (size_t)row0 * CAP);
        uint2* sC2 = reinterpret_cast<uint2*>(sC);
        for (int i = tid; i < RPB * CAP / 4; i += 256) sC2[i] = gc2[i];
        const float4* gv4 = reinterpret_cast<const float4*>(g_vals + (size_t)row0 * CAP);
        float4* sV4 = reinterpret_cast<float4*>(sV);
        for (int i = tid; i < RPB * CAP / 4; i += 256) sV4[i] = gv4[i];
        if (FINAL) {
            const float4* gm4 = reinterpret_cast<const float4*>(g_M);
            float4* sM4 = reinterpret_cast<float4*>(sM);
            #pragma unroll
            for (int j = 0; j < (DD * DD / 4) / 256; ++j)
                sM4[j * 256 + tid] = gm4[j * 256 + tid];
        }
    }
    __syncthreads();

    int r = tid >> 4, l = tid & 15;
    int cnt = sCnt[r];
    const unsigned short* cr = sC + r * CAP;
    const float*          vr = sV + r * CAP;
    const float4* x4 = reinterpret_cast<const float4*>(xin);

    float4 a0 = make_float4(0.f,0.f,0.f,0.f), a1 = a0, a2 = a0, a3 = a0;
    int k = 0;
    for (; k + 8 <= cnt; k += 8) {
        int   c0 = cr[k],   c1 = cr[k+1], c2 = cr[k+2], c3 = cr[k+3];
        int   c4 = cr[k+4], c5 = cr[k+5], c6 = cr[k+6], c7 = cr[k+7];
        float v0 = vr[k],   v1 = vr[k+1], v2 = vr[k+2], v3 = vr[k+3];
        float v4 = vr[k+4], v5 = vr[k+5], v6 = vr[k+6], v7 = vr[k+7];
        float4 g0 = __ldg(&x4[c0 * 16 + l]);
        float4 g1 = __ldg(&x4[c1 * 16 + l]);
        float4 g2 = __ldg(&x4[c2 * 16 + l]);
        float4 g3 = __ldg(&x4[c3 * 16 + l]);
        float4 g4 = __ldg(&x4[c4 * 16 + l]);
        float4 g5 = __ldg(&x4[c5 * 16 + l]);
        float4 g6 = __ldg(&x4[c6 * 16 + l]);
        float4 g7 = __ldg(&x4[c7 * 16 + l]);
        a0.x += v0*g0.x; a0.y += v0*g0.y; a0.z += v0*g0.z; a0.w += v0*g0.w;
        a1.x += v1*g1.x; a1.y += v1*g1.y; a1.z += v1*g1.z; a1.w += v1*g1.w;
        a2.x += v2*g2.x; a2.y += v2*g2.y; a2.z += v2*g2.z; a2.w += v2*g2.w;
        a3.x += v3*g3.x; a3.y += v3*g3.y; a3.z += v3*g3.z; a3.w += v3*g3.w;
        a0.x += v4*g4.x; a0.y += v4*g4.y; a0.z += v4*g4.z; a0.w += v4*g4.w;
        a1.x += v5*g5.x; a1.y += v5*g5.y; a1.z += v5*g5.z; a1.w += v5*g5.w;
        a2.x += v6*g6.x; a2.y += v6*g6.y; a2.z += v6*g6.z; a2.w += v6*g6.w;
        a3.x += v7*g7.x; a3.y += v7*g7.y; a3.z += v7*g7.z; a3.w += v7*g7.w;
    }
    for (; k < cnt; ++k) {
        int c = cr[k]; float v = vr[k];
        float4 g = __ldg(&x4[c * 16 + l]);
        a0.x += v*g.x; a0.y += v*g.y; a0.z += v*g.z; a0.w += v*g.w;
    }
    float4 y;
    y.x = (a0.x + a1.x) + (a2.x + a3.x);
    y.y = (a0.y + a1.y) + (a2.y + a3.y);
    y.z = (a0.z + a1.z) + (a2.z + a3.z);
    y.w = (a0.w + a1.w) + (a2.w + a3.w);

    int row = row0 + r;

    if (S2) {
        float s2a = 0.0f;
        for (int kk = l; kk < cnt; kk += 16)
            s2a += vr[kk] * __ldg(&g_s1[cr[kk]]);
        #pragma unroll
        for (int o = 8; o; o >>= 1) s2a += __shfl_xor_sync(0xffffffffu, s2a, o);
        if (l == 0) g_s2[row] = s2a;
    }

    if (!FINAL) {
        reinterpret_cast<float4*>(xout)[(size_t)row * 16 + l] = y;
    } else {
        reinterpret_cast<float4*>(&shY[r][0])[l] = y;
        __syncthreads();

        float s1v = g_s1[row], s2v = g_s2[row];
        float4 c0v = reinterpret_cast<const float4*>(g_c0)[l];
        float4 c1v = reinterpret_cast<const float4*>(g_c1)[l];
        float4 bv  = __ldg(&reinterpret_cast<const float4*>(b2)[l]);

        float4 acc;
        acc.x = s2v * c0v.x + s1v * c1v.x + bv.x;
        acc.y = s2v * c0v.y + s1v * c1v.y + bv.y;
        acc.z = s2v * c0v.z + s1v * c1v.z + bv.z;
        acc.w = s2v * c0v.w + s1v * c1v.w + bv.w;

        #pragma unroll 8
        for (int d = 0; d < DD; ++d) {
            float yd  = shY[r][d];
            float4 m4 = reinterpret_cast<const float4*>(sM + d * DD)[l];
            acc.x += yd * m4.x; acc.y += yd * m4.y;
            acc.z += yd * m4.z; acc.w += yd * m4.w;
        }
        reinterpret_cast<float4*>(xout)[(size_t)row * 16 + l] = acc;
    }
}

// ============================================================================
// Launch (4 kernels)
// ============================================================================
extern "C" void kernel_launch(void* const* d_in, const int* in_sizes, int n_in,
                              void* d_out, int out_size) {
    const float* x  = (const float*)d_in[0];
    const float* A  = (const float*)d_in[1];
    const float* LW = (const float*)d_in[2];
    const float* W0 = (const float*)d_in[3];
    const float* b0 = (const float*)d_in[4];
    const float* W1 = (const float*)d_in[5];
    const float* b1 = (const float*)d_in[6];
    const float* W2 = (const float*)d_in[7];
    const float* b2 = (const float*)d_in[8];
    float* out = (float*)d_out;

    float* buf0; cudaGetSymbolAddress((void**)&buf0, g_buf0);
    float* buf1; cudaGetSymbolAddress((void**)&buf1, g_buf1);

    build_kernel<<<NN / 8, 256>>>(A, LW, x, buf0);  // ELL + s1 + y1 = w x
    prep_kernel <<<16, 256>>>(W0, W1, b0, W2, b1);  // M, c0, c1

    spmm_kernel<true,  false><<<NN / RPB, 256>>>(buf0, buf1, nullptr);  // y2 + s2
    spmm_kernel<false, true ><<<NN / RPB, 256>>>(buf1, out,  b2);       // out
}

// round 8
// speedup vs baseline: 1.1135x; 1.1135x over previous
#include <cuda_runtime.h>

// MaskedCommonWeightSimpleLinearGNN:
//   w = LW * A (binary mask ~1%, 8192x8192), same w for all 3 layers.
//   out = (w^3 x) M + (w^2 1) c0^T + (w 1) c1^T + 1 b2^T
//     M = W0^T W1^T W2^T, c0 = W2 W1 b0, c1 = W2 b1
// Pipeline (5 launches, R6 structure):
//   build  : scan A -> per-lane private slots (NO ballots; order-free, fp32
//            sum reorder ~1e-7 << 1e-3 tol) -> one warp-scan compaction ->
//            gather LW -> cols/vals/s1
//   prep   : M, c0, c1
//   spmm x3: layer1, layer2 (+strided s2), layer3 (fused M + rank-1 epilogue)

#define NN   8192
#define DD   64
#define CAP  160      // Binomial(8192,0.01): mean 82, sigma 9 -> mean+8.7sigma
#define RPB  16
#define PRIV 20       // per-lane slots; Binomial(256,0.01) mean 2.56 -> +11sigma

// ---- allocation-free scratch ----
__device__ unsigned short g_cols[(size_t)NN * CAP];
__device__ float          g_vals[(size_t)NN * CAP];
__device__ int            g_cnt[NN];
__device__ float          g_s1[NN];
__device__ float          g_s2[NN];
__device__ float          g_M[DD * DD];
__device__ float          g_c0[DD];
__device__ float          g_c1[DD];
__device__ float          g_buf0[(size_t)NN * DD];
__device__ float          g_buf1[(size_t)NN * DD];

// ============================================================================
// 1) build: one warp per row.
//    a) stream A (float4, prefetch depth 1); each lane appends its nonzero
//       columns to a private transposed SMEM list slot[cnt][lane]
//       (bank-conflict-free, ~3 instr per element, no ballots in the loop)
//    b) ONE warp scan to compact lane lists -> wc[]
//    c) gather LW at nonzeros -> vals + s1 row sum, coalesced writeout
// ============================================================================
__global__ void __launch_bounds__(256)
build_kernel(const float* __restrict__ A, const float* __restrict__ LW) {
    __shared__ unsigned short sPriv[8][PRIV][32];   // 10 KB
    __shared__ unsigned short sCols[8][CAP];        // 2.5 KB

    int wid  = threadIdx.x >> 5;
    int lane = threadIdx.x & 31;
    int row  = blockIdx.x * 8 + wid;

    const float4* a4 = reinterpret_cast<const float4*>(A + (size_t)row * NN);
    unsigned short (*priv)[32] = sPriv[wid];
    unsigned short* wc = sCols[wid];

    // --- a) scan with per-lane private append ---
    int myc = 0;
    float4 cur = a4[lane];
    for (int c = 0; c < NN / 128; ++c) {
        float4 nxt;
        if (c + 1 < NN / 128) nxt = a4[(c + 1) * 32 + lane];

        int cb = c * 128 + lane * 4;
        if (cur.x != 0.0f) { if (myc < PRIV) priv[myc][lane] = (unsigned short)(cb    ); ++myc; }
        if (cur.y != 0.0f) { if (myc < PRIV) priv[myc][lane] = (unsigned short)(cb + 1); ++myc; }
        if (cur.z != 0.0f) { if (myc < PRIV) priv[myc][lane] = (unsigned short)(cb + 2); ++myc; }
        if (cur.w != 0.0f) { if (myc < PRIV) priv[myc][lane] = (unsigned short)(cb + 3); ++myc; }
        cur = nxt;
    }
    if (myc > PRIV) myc = PRIV;

    // --- b) one warp scan + compaction ---
    int inc = myc;
    #pragma unroll
    for (int o = 1; o < 32; o <<= 1) {
        int t = __shfl_up_sync(0xffffffffu, inc, o);
        if (lane >= o) inc += t;
    }
    int base = inc - myc;
    int cnt  = __shfl_sync(0xffffffffu, inc, 31);
    if (cnt > CAP) cnt = CAP;
    for (int j = 0; j < myc; ++j) {
        int p = base + j;
        if (p < CAP) wc[p] = priv[j][lane];
    }
    __syncwarp();

    // --- c) gather LW, coalesced writeout, row sum ---
    const float* lw = LW + (size_t)row * NN;
    unsigned short* gcols = g_cols + (size_t)row * CAP;
    float*          gvals = g_vals + (size_t)row * CAP;

    float s = 0.0f;
    #pragma unroll
    for (int j = 0; j < CAP / 32; ++j) {
        int k = j * 32 + lane;
        if (k < cnt) {
            unsigned short c = wc[k];
            float v = __ldg(&lw[c]);
            gvals[k] = v;
            gcols[k] = c;
            s += v;
        }
    }
    #pragma unroll
    for (int o = 16; o; o >>= 1) s += __shfl_xor_sync(0xffffffffu, s, o);
    if (lane == 0) {
        g_cnt[row] = cnt;
        g_s1[row]  = s;
    }
}

// ============================================================================
// 2) prep: M = W0^T W1^T W2^T, c0 = W2 W1 b0, c1 = W2 b1.
//    16 blocks x 256 threads; padded shared (stride 65) -> conflict-free.
// ============================================================================
__global__ void __launch_bounds__(256)
prep_kernel(const float* __restrict__ W0, const float* __restrict__ W1,
            const float* __restrict__ b0, const float* __restrict__ W2,
            const float* __restrict__ b1) {
    __shared__ float sW0[DD * DD];        // [f*64+d], d const per warp -> broadcast
    __shared__ float sW1[DD * 65];
    __shared__ float sW2[DD * 65];
    __shared__ float sP[4 * 65];
    __shared__ float sQ[DD];

    int tid = threadIdx.x;
    for (int i = tid; i < DD * DD; i += 256) {
        sW0[i] = W0[i];
        sW1[(i >> 6) * 65 + (i & 63)] = W1[i];
        sW2[(i >> 6) * 65 + (i & 63)] = W2[i];
    }
    __syncthreads();

    int dl = tid >> 6;
    int e  = tid & 63;
    int d  = blockIdx.x * 4 + dl;

    float p = 0.0f;
    #pragma unroll
    for (int f = 0; f < DD; ++f) p += sW0[f * DD + d] * sW1[e * 65 + f];
    sP[dl * 65 + e] = p;

    if (blockIdx.x == 0 && tid < DD) {
        float s = 0.0f;
        #pragma unroll
        for (int f = 0; f < DD; ++f) s += sW1[tid * 65 + f] * __ldg(&b0[f]);
        sQ[tid] = s;
    }
    __syncthreads();

    int t = e;
    float msum = 0.0f;
    #pragma unroll
    for (int ee = 0; ee < DD; ++ee) msum += sP[dl * 65 + ee] * sW2[t * 65 + ee];
    g_M[d * DD + t] = msum;

    if (blockIdx.x == 0 && tid < DD) {
        float s0 = 0.0f, s1v = 0.0f;
        #pragma unroll
        for (int ee = 0; ee < DD; ++ee) {
            float w2 = sW2[tid * 65 + ee];
            s0  += w2 * sQ[ee];
            s1v += w2 * __ldg(&b1[ee]);
        }
        g_c0[tid] = s0;
        g_c1[tid] = s1v;
    }
}

// ============================================================================
// 3) SpMM template. 16 rows/block, 256 threads (16 lanes/row).
//    cols (ushort) + vals staged in shared; 8-way unrolled float4 gathers.
//    S2: strided post-loop computing s2 = w s1.
//    FINAL: fused epilogue out = y M + s2 c0^T + s1 c1^T + b2.
// ============================================================================
template <bool S2, bool FINAL>
__global__ void __launch_bounds__(256)
spmm_kernel(const float* __restrict__ xin, float* __restrict__ xout,
            const float* __restrict__ b2) {
    __shared__ unsigned short sC[RPB * CAP];     // 5 KB
    __shared__ float          sV[RPB * CAP];     // 10 KB
    __shared__ int            sCnt[RPB];
    __shared__ float          sM[FINAL ? DD * DD : 1];
    __shared__ float          shY[FINAL ? RPB : 1][DD];

    int tid  = threadIdx.x;
    int row0 = blockIdx.x * RPB;

    if (tid < RPB) sCnt[tid] = g_cnt[row0 + tid];

    {
        const uint2* gc2 = reinterpret_cast<const uint2*>(g_cols + (size_t)row0 * CAP);
        uint2* sC2 = reinterpret_cast<uint2*>(sC);
        for (int i = tid; i < RPB * CAP / 4; i += 256) sC2[i] = gc2[i];
        const float4* gv4 = reinterpret_cast<const float4*>(g_vals + (size_t)row0 * CAP);
        float4* sV4 = reinterpret_cast<float4*>(sV);
        for (int i = tid; i < RPB * CAP / 4; i += 256) sV4[i] = gv4[i];
        if (FINAL) {
            const float4* gm4 = reinterpret_cast<const float4*>(g_M);
            float4* sM4 = reinterpret_cast<float4*>(sM);
            #pragma unroll
            for (int j = 0; j < (DD * DD / 4) / 256; ++j)
                sM4[j * 256 + tid] = gm4[j * 256 + tid];
        }
    }
    __syncthreads();

    int r = tid >> 4, l = tid & 15;
    int cnt = sCnt[r];
    const unsigned short* cr = sC + r * CAP;
    const float*          vr = sV + r * CAP;
    const float4* x4 = reinterpret_cast<const float4*>(xin);

    float4 a0 = make_float4(0.f,0.f,0.f,0.f), a1 = a0, a2 = a0, a3 = a0;
    int k = 0;
    for (; k + 8 <= cnt; k += 8) {
        int   c0 = cr[k],   c1 = cr[k+1], c2 = cr[k+2], c3 = cr[k+3];
        int   c4 = cr[k+4], c5 = cr[k+5], c6 = cr[k+6], c7 = cr[k+7];
        float v0 = vr[k],   v1 = vr[k+1], v2 = vr[k+2], v3 = vr[k+3];
        float v4 = vr[k+4], v5 = vr[k+5], v6 = vr[k+6], v7 = vr[k+7];
        float4 g0 = __ldg(&x4[c0 * 16 + l]);
        float4 g1 = __ldg(&x4[c1 * 16 + l]);
        float4 g2 = __ldg(&x4[c2 * 16 + l]);
        float4 g3 = __ldg(&x4[c3 * 16 + l]);
        float4 g4 = __ldg(&x4[c4 * 16 + l]);
        float4 g5 = __ldg(&x4[c5 * 16 + l]);
        float4 g6 = __ldg(&x4[c6 * 16 + l]);
        float4 g7 = __ldg(&x4[c7 * 16 + l]);
        a0.x += v0*g0.x; a0.y += v0*g0.y; a0.z += v0*g0.z; a0.w += v0*g0.w;
        a1.x += v1*g1.x; a1.y += v1*g1.y; a1.z += v1*g1.z; a1.w += v1*g1.w;
        a2.x += v2*g2.x; a2.y += v2*g2.y; a2.z += v2*g2.z; a2.w += v2*g2.w;
        a3.x += v3*g3.x; a3.y += v3*g3.y; a3.z += v3*g3.z; a3.w += v3*g3.w;
        a0.x += v4*g4.x; a0.y += v4*g4.y; a0.z += v4*g4.z; a0.w += v4*g4.w;
        a1.x += v5*g5.x; a1.y += v5*g5.y; a1.z += v5*g5.z; a1.w += v5*g5.w;
        a2.x += v6*g6.x; a2.y += v6*g6.y; a2.z += v6*g6.z; a2.w += v6*g6.w;
        a3.x += v7*g7.x; a3.y += v7*g7.y; a3.z += v7*g7.z; a3.w += v7*g7.w;
    }
    for (; k < cnt; ++k) {
        int c = cr[k]; float v = vr[k];
        float4 g = __ldg(&x4[c * 16 + l]);
        a0.x += v*g.x; a0.y += v*g.y; a0.z += v*g.z; a0.w += v*g.w;
    }
    float4 y;
    y.x = (a0.x + a1.x) + (a2.x + a3.x);
    y.y = (a0.y + a1.y) + (a2.y + a3.y);
    y.z = (a0.z + a1.z) + (a2.z + a3.z);
    y.w = (a0.w + a1.w) + (a2.w + a3.w);

    int row = row0 + r;

    if (S2) {
        float s2a = 0.0f;
        for (int kk = l; kk < cnt; kk += 16)
            s2a += vr[kk] * __ldg(&g_s1[cr[kk]]);
        #pragma unroll
        for (int o = 8; o; o >>= 1) s2a += __shfl_xor_sync(0xffffffffu, s2a, o);
        if (l == 0) g_s2[row] = s2a;
    }

    if (!FINAL) {
        reinterpret_cast<float4*>(xout)[(size_t)row * 16 + l] = y;
    } else {
        reinterpret_cast<float4*>(&shY[r][0])[l] = y;
        __syncthreads();

        float s1v = g_s1[row], s2v = g_s2[row];
        float4 c0v = reinterpret_cast<const float4*>(g_c0)[l];
        float4 c1v = reinterpret_cast<const float4*>(g_c1)[l];
        float4 bv  = __ldg(&reinterpret_cast<const float4*>(b2)[l]);

        float4 acc;
        acc.x = s2v * c0v.x + s1v * c1v.x + bv.x;
        acc.y = s2v * c0v.y + s1v * c1v.y + bv.y;
        acc.z = s2v * c0v.z + s1v * c1v.z + bv.z;
        acc.w = s2v * c0v.w + s1v * c1v.w + bv.w;

        #pragma unroll 8
        for (int d = 0; d < DD; ++d) {
            float yd  = shY[r][d];
            float4 m4 = reinterpret_cast<const float4*>(sM + d * DD)[l];
            acc.x += yd * m4.x; acc.y += yd * m4.y;
            acc.z += yd * m4.z; acc.w += yd * m4.w;
        }
        reinterpret_cast<float4*>(xout)[(size_t)row * 16 + l] = acc;
    }
}

// ============================================================================
// Launch (5 kernels)
// ============================================================================
extern "C" void kernel_launch(void* const* d_in, const int* in_sizes, int n_in,
                              void* d_out, int out_size) {
    const float* x  = (const float*)d_in[0];
    const float* A  = (const float*)d_in[1];
    const float* LW = (const float*)d_in[2];
    const float* W0 = (const float*)d_in[3];
    const float* b0 = (const float*)d_in[4];
    const float* W1 = (const float*)d_in[5];
    const float* b1 = (const float*)d_in[6];
    const float* W2 = (const float*)d_in[7];
    const float* b2 = (const float*)d_in[8];
    float* out = (float*)d_out;

    float* buf0; cudaGetSymbolAddress((void**)&buf0, g_buf0);
    float* buf1; cudaGetSymbolAddress((void**)&buf1, g_buf1);

    build_kernel<<<NN / 8, 256>>>(A, LW);           // cols/vals/cnt/s1
    prep_kernel <<<16, 256>>>(W0, W1, b0, W2, b1);  // M, c0, c1

    spmm_kernel<false, false><<<NN / RPB, 256>>>(x,    buf0, nullptr);  // y1
    spmm_kernel<true,  false><<<NN / RPB, 256>>>(buf0, buf1, nullptr);  // y2 + s2
    spmm_kernel<false, true ><<<NN / RPB, 256>>>(buf1, out,  b2);       // out
}

// round 9
// speedup vs baseline: 1.1698x; 1.0506x over previous
#include <cuda_runtime.h>

// MaskedCommonWeightSimpleLinearGNN:
//   w = LW * A (binary mask ~1%, 8192x8192), same w for all 3 layers.
//   out = (w^3 x) M + (w^2 1) c0^T + (w 1) c1^T + 1 b2^T
//     M = W0^T W1^T W2^T, c0 = W2 W1 b0, c1 = W2 b1
// Pipeline (5 launches):
//   build  : stream A 512 cols/iter with 4 float4 prefetches in flight
//            (2KB/warp -> ~14MB chip-wide, saturates DRAM) -> per-lane
//            private slots -> one warp-scan compaction -> gather LW -> s1
//   prep   : M, c0, c1
//   spmm x3: layer1, layer2 (+strided s2), layer3 (fused M + rank-1 epilogue)

#define NN   8192
#define DD   64
#define CAP  160      // Binomial(8192,0.01): mean 82, sigma 9 -> mean+8.7sigma
#define RPB  16
#define PRIV 20       // per-lane slots; Binomial(256,0.01) mean 2.56 -> +11sigma

// ---- allocation-free scratch ----
__device__ unsigned short g_cols[(size_t)NN * CAP];
__device__ float          g_vals[(size_t)NN * CAP];
__device__ int            g_cnt[NN];
__device__ float          g_s1[NN];
__device__ float          g_s2[NN];
__device__ float          g_M[DD * DD];
__device__ float          g_c0[DD];
__device__ float          g_c1[DD];
__device__ float          g_buf0[(size_t)NN * DD];
__device__ float          g_buf1[(size_t)NN * DD];

// evict-first streaming load of a float4
__device__ __forceinline__ float4 ldcs4(const float4* p) {
    return __ldcs(p);
}

// ============================================================================
// 1) build: one warp per row.
//    a) stream A: 16 iterations x 512 cols (4 float4/lane), 4 loads in
//       flight per lane -> 2KB/warp in flight; per-lane private append
//    b) one warp scan to compact lane lists
//    c) gather LW at nonzeros -> vals + s1, coalesced writeout
// ============================================================================
__global__ void __launch_bounds__(256)
build_kernel(const float* __restrict__ A, const float* __restrict__ LW) {
    __shared__ unsigned short sPriv[8][PRIV][32];   // 10 KB
    __shared__ unsigned short sCols[8][CAP];        // 2.5 KB

    int wid  = threadIdx.x >> 5;
    int lane = threadIdx.x & 31;
    int row  = blockIdx.x * 8 + wid;

    const float4* a4 = reinterpret_cast<const float4*>(A + (size_t)row * NN);
    unsigned short (*priv)[32] = sPriv[wid];
    unsigned short* wc = sCols[wid];

    // --- a) scan: 512 cols per iteration, 4 prefetched float4 per lane ---
    int myc = 0;
    float4 c0 = ldcs4(&a4[lane]);
    float4 c1 = ldcs4(&a4[32 + lane]);
    float4 c2 = ldcs4(&a4[64 + lane]);
    float4 c3 = ldcs4(&a4[96 + lane]);

    #pragma unroll 1
    for (int it = 0; it < NN / 512; ++it) {
        float4 n0, n1, n2, n3;
        if (it + 1 < NN / 512) {
            int nb = (it + 1) * 128;
            n0 = ldcs4(&a4[nb + lane]);
            n1 = ldcs4(&a4[nb + 32 + lane]);
            n2 = ldcs4(&a4[nb + 64 + lane]);
            n3 = ldcs4(&a4[nb + 96 + lane]);
        }
        int b0 = it * 512 + lane * 4;
        {
            if (c0.x != 0.0f) { if (myc < PRIV) priv[myc][lane] = (unsigned short)(b0    ); ++myc; }
            if (c0.y != 0.0f) { if (myc < PRIV) priv[myc][lane] = (unsigned short)(b0 + 1); ++myc; }
            if (c0.z != 0.0f) { if (myc < PRIV) priv[myc][lane] = (unsigned short)(b0 + 2); ++myc; }
            if (c0.w != 0.0f) { if (myc < PRIV) priv[myc][lane] = (unsigned short)(b0 + 3); ++myc; }
        }
        int b1 = b0 + 128;
        {
            if (c1.x != 0.0f) { if (myc < PRIV) priv[myc][lane] = (unsigned short)(b1    ); ++myc; }
            if (c1.y != 0.0f) { if (myc < PRIV) priv[myc][lane] = (unsigned short)(b1 + 1); ++myc; }
            if (c1.z != 0.0f) { if (myc < PRIV) priv[myc][lane] = (unsigned short)(b1 + 2); ++myc; }
            if (c1.w != 0.0f) { if (myc < PRIV) priv[myc][lane] = (unsigned short)(b1 + 3); ++myc; }
        }
        int b2 = b0 + 256;
        {
            if (c2.x != 0.0f) { if (myc < PRIV) priv[myc][lane] = (unsigned short)(b2    ); ++myc; }
            if (c2.y != 0.0f) { if (myc < PRIV) priv[myc][lane] = (unsigned short)(b2 + 1); ++myc; }
            if (c2.z != 0.0f) { if (myc < PRIV) priv[myc][lane] = (unsigned short)(b2 + 2); ++myc; }
            if (c2.w != 0.0f) { if (myc < PRIV) priv[myc][lane] = (unsigned short)(b2 + 3); ++myc; }
        }
        int b3 = b0 + 384;
        {
            if (c3.x != 0.0f) { if (myc < PRIV) priv[myc][lane] = (unsigned short)(b3    ); ++myc; }
            if (c3.y != 0.0f) { if (myc < PRIV) priv[myc][lane] = (unsigned short)(b3 + 1); ++myc; }
            if (c3.z != 0.0f) { if (myc < PRIV) priv[myc][lane] = (unsigned short)(b3 + 2); ++myc; }
            if (c3.w != 0.0f) { if (myc < PRIV) priv[myc][lane] = (unsigned short)(b3 + 3); ++myc; }
        }
        c0 = n0; c1 = n1; c2 = n2; c3 = n3;
    }
    if (myc > PRIV) myc = PRIV;

    // --- b) one warp scan + compaction ---
    int inc = myc;
    #pragma unroll
    for (int o = 1; o < 32; o <<= 1) {
        int t = __shfl_up_sync(0xffffffffu, inc, o);
        if (lane >= o) inc += t;
    }
    int base = inc - myc;
    int cnt  = __shfl_sync(0xffffffffu, inc, 31);
    if (cnt > CAP) cnt = CAP;
    for (int j = 0; j < myc; ++j) {
        int p = base + j;
        if (p < CAP) wc[p] = priv[j][lane];
    }
    __syncwarp();

    // --- c) gather LW, coalesced writeout, row sum ---
    const float* lw = LW + (size_t)row * NN;
    unsigned short* gcols = g_cols + (size_t)row * CAP;
    float*          gvals = g_vals + (size_t)row * CAP;

    float s = 0.0f;
    #pragma unroll
    for (int j = 0; j < CAP / 32; ++j) {
        int k = j * 32 + lane;
        if (k < cnt) {
            unsigned short c = wc[k];
            float v = __ldcs(&lw[c]);
            gvals[k] = v;
            gcols[k] = c;
            s += v;
        }
    }
    #pragma unroll
    for (int o = 16; o; o >>= 1) s += __shfl_xor_sync(0xffffffffu, s, o);
    if (lane == 0) {
        g_cnt[row] = cnt;
        g_s1[row]  = s;
    }
}

// ============================================================================
// 2) prep: M = W0^T W1^T W2^T, c0 = W2 W1 b0, c1 = W2 b1.
//    16 blocks x 256 threads; padded shared (stride 65) -> conflict-free.
// ============================================================================
__global__ void __launch_bounds__(256)
prep_kernel(const float* __restrict__ W0, const float* __restrict__ W1,
            const float* __restrict__ b0, const float* __restrict__ W2,
            const float* __restrict__ b1) {
    __shared__ float sW0[DD * DD];        // [f*64+d], d const per warp -> broadcast
    __shared__ float sW1[DD * 65];
    __shared__ float sW2[DD * 65];
    __shared__ float sP[4 * 65];
    __shared__ float sQ[DD];

    int tid = threadIdx.x;
    for (int i = tid; i < DD * DD; i += 256) {
        sW0[i] = W0[i];
        sW1[(i >> 6) * 65 + (i & 63)] = W1[i];
        sW2[(i >> 6) * 65 + (i & 63)] = W2[i];
    }
    __syncthreads();

    int dl = tid >> 6;
    int e  = tid & 63;
    int d  = blockIdx.x * 4 + dl;

    float p = 0.0f;
    #pragma unroll
    for (int f = 0; f < DD; ++f) p += sW0[f * DD + d] * sW1[e * 65 + f];
    sP[dl * 65 + e] = p;

    if (blockIdx.x == 0 && tid < DD) {
        float s = 0.0f;
        #pragma unroll
        for (int f = 0; f < DD; ++f) s += sW1[tid * 65 + f] * __ldg(&b0[f]);
        sQ[tid] = s;
    }
    __syncthreads();

    int t = e;
    float msum = 0.0f;
    #pragma unroll
    for (int ee = 0; ee < DD; ++ee) msum += sP[dl * 65 + ee] * sW2[t * 65 + ee];
    g_M[d * DD + t] = msum;

    if (blockIdx.x == 0 && tid < DD) {
        float s0 = 0.0f, s1v = 0.0f;
        #pragma unroll
        for (int ee = 0; ee < DD; ++ee) {
            float w2 = sW2[tid * 65 + ee];
            s0  += w2 * sQ[ee];
            s1v += w2 * __ldg(&b1[ee]);
        }
        g_c0[tid] = s0;
        g_c1[tid] = s1v;
    }
}

// ============================================================================
// 3) SpMM template. 16 rows/block, 256 threads (16 lanes/row).
//    cols (ushort) + vals staged in shared; 8-way unrolled float4 gathers.
//    S2: strided post-loop computing s2 = w s1.
//    FINAL: fused epilogue out = y M + s2 c0^T + s1 c1^T + b2.
// ============================================================================
template <bool S2, bool FINAL>
__global__ void __launch_bounds__(256)
spmm_kernel(const float* __restrict__ xin, float* __restrict__ xout,
            const float* __restrict__ b2) {
    __shared__ unsigned short sC[RPB * CAP];     // 5 KB
    __shared__ float          sV[RPB * CAP];     // 10 KB
    __shared__ int            sCnt[RPB];
    __shared__ float          sM[FINAL ? DD * DD : 1];
    __shared__ float          shY[FINAL ? RPB : 1][DD];

    int tid  = threadIdx.x;
    int row0 = blockIdx.x * RPB;

    if (tid < RPB) sCnt[tid] = g_cnt[row0 + tid];

    {
        const uint2* gc2 = reinterpret_cast<const uint2*>(g_cols + (size_t)row0 * CAP);
        uint2* sC2 = reinterpret_cast<uint2*>(sC);
        for (int i = tid; i < RPB * CAP / 4; i += 256) sC2[i] = gc2[i];
        const float4* gv4 = reinterpret_cast<const float4*>(g_vals + (size_t)row0 * CAP);
        float4* sV4 = reinterpret_cast<float4*>(sV);
        for (int i = tid; i < RPB * CAP / 4; i += 256) sV4[i] = gv4[i];
        if (FINAL) {
            const float4* gm4 = reinterpret_cast<const float4*>(g_M);
            float4* sM4 = reinterpret_cast<float4*>(sM);
            #pragma unroll
            for (int j = 0; j < (DD * DD / 4) / 256; ++j)
                sM4[j * 256 + tid] = gm4[j * 256 + tid];
        }
    }
    __syncthreads();

    int r = tid >> 4, l = tid & 15;
    int cnt = sCnt[r];
    const unsigned short* cr = sC + r * CAP;
    const float*          vr = sV + r * CAP;
    const float4* x4 = reinterpret_cast<const float4*>(xin);

    float4 a0 = make_float4(0.f,0.f,0.f,0.f), a1 = a0, a2 = a0, a3 = a0;
    int k = 0;
    for (; k + 8 <= cnt; k += 8) {
        int   c0 = cr[k],   c1 = cr[k+1], c2 = cr[k+2], c3 = cr[k+3];
        int   c4 = cr[k+4], c5 = cr[k+5], c6 = cr[k+6], c7 = cr[k+7];
        float v0 = vr[k],   v1 = vr[k+1], v2 = vr[k+2], v3 = vr[k+3];
        float v4 = vr[k+4], v5 = vr[k+5], v6 = vr[k+6], v7 = vr[k+7];
        float4 g0 = __ldg(&x4[c0 * 16 + l]);
        float4 g1 = __ldg(&x4[c1 * 16 + l]);
        float4 g2 = __ldg(&x4[c2 * 16 + l]);
        float4 g3 = __ldg(&x4[c3 * 16 + l]);
        float4 g4 = __ldg(&x4[c4 * 16 + l]);
        float4 g5 = __ldg(&x4[c5 * 16 + l]);
        float4 g6 = __ldg(&x4[c6 * 16 + l]);
        float4 g7 = __ldg(&x4[c7 * 16 + l]);
        a0.x += v0*g0.x; a0.y += v0*g0.y; a0.z += v0*g0.z; a0.w += v0*g0.w;
        a1.x += v1*g1.x; a1.y += v1*g1.y; a1.z += v1*g1.z; a1.w += v1*g1.w;
        a2.x += v2*g2.x; a2.y += v2*g2.y; a2.z += v2*g2.z; a2.w += v2*g2.w;
        a3.x += v3*g3.x; a3.y += v3*g3.y; a3.z += v3*g3.z; a3.w += v3*g3.w;
        a0.x += v4*g4.x; a0.y += v4*g4.y; a0.z += v4*g4.z; a0.w += v4*g4.w;
        a1.x += v5*g5.x; a1.y += v5*g5.y; a1.z += v5*g5.z; a1.w += v5*g5.w;
        a2.x += v6*g6.x; a2.y += v6*g6.y; a2.z += v6*g6.z; a2.w += v6*g6.w;
        a3.x += v7*g7.x; a3.y += v7*g7.y; a3.z += v7*g7.z; a3.w += v7*g7.w;
    }
    for (; k < cnt; ++k) {
        int c = cr[k]; float v = vr[k];
        float4 g = __ldg(&x4[c * 16 + l]);
        a0.x += v*g.x; a0.y += v*g.y; a0.z += v*g.z; a0.w += v*g.w;
    }
    float4 y;
    y.x = (a0.x + a1.x) + (a2.x + a3.x);
    y.y = (a0.y + a1.y) + (a2.y + a3.y);
    y.z = (a0.z + a1.z) + (a2.z + a3.z);
    y.w = (a0.w + a1.w) + (a2.w + a3.w);

    int row = row0 + r;

    if (S2) {
        float s2a = 0.0f;
        for (int kk = l; kk < cnt; kk += 16)
            s2a += vr[kk] * __ldg(&g_s1[cr[kk]]);
        #pragma unroll
        for (int o = 8; o; o >>= 1) s2a += __shfl_xor_sync(0xffffffffu, s2a, o);
        if (l == 0) g_s2[row] = s2a;
    }

    if (!FINAL) {
        reinterpret_cast<float4*>(xout)[(size_t)row * 16 + l] = y;
    } else {
        reinterpret_cast<float4*>(&shY[r][0])[l] = y;
        __syncthreads();

        float s1v = g_s1[row], s2v = g_s2[row];
        float4 c0v = reinterpret_cast<const float4*>(g_c0)[l];
        float4 c1v = reinterpret_cast<const float4*>(g_c1)[l];
        float4 bv  = __ldg(&reinterpret_cast<const float4*>(b2)[l]);

        float4 acc;
        acc.x = s2v * c0v.x + s1v * c1v.x + bv.x;
        acc.y = s2v * c0v.y + s1v * c1v.y + bv.y;
        acc.z = s2v * c0v.z + s1v * c1v.z + bv.z;
        acc.w = s2v * c0v.w + s1v * c1v.w + bv.w;

        #pragma unroll 8
        for (int d = 0; d < DD; ++d) {
            float yd  = shY[r][d];
            float4 m4 = reinterpret_cast<const float4*>(sM + d * DD)[l];
            acc.x += yd * m4.x; acc.y += yd * m4.y;
            acc.z += yd * m4.z; acc.w += yd * m4.w;
        }
        reinterpret_cast<float4*>(xout)[(size_t)row * 16 + l] = acc;
    }
}

// ============================================================================
// Launch (5 kernels)
// ============================================================================
extern "C" void kernel_launch(void* const* d_in, const int* in_sizes, int n_in,
                              void* d_out, int out_size) {
    const float* x  = (const float*)d_in[0];
    const float* A  = (const float*)d_in[1];
    const float* LW = (const float*)d_in[2];
    const float* W0 = (const float*)d_in[3];
    const float* b0 = (const float*)d_in[4];
    const float* W1 = (const float*)d_in[5];
    const float* b1 = (const float*)d_in[6];
    const float* W2 = (const float*)d_in[7];
    const float* b2 = (const float*)d_in[8];
    float* out = (float*)d_out;

    float* buf0; cudaGetSymbolAddress((void**)&buf0, g_buf0);
    float* buf1; cudaGetSymbolAddress((void**)&buf1, g_buf1);

    build_kernel<<<NN / 8, 256>>>(A, LW);           // cols/vals/cnt/s1
    prep_kernel <<<16, 256>>>(W0, W1, b0, W2, b1);  // M, c0, c1

    spmm_kernel<false, false><<<NN / RPB, 256>>>(x,    buf0, nullptr);  // y1
    spmm_kernel<true,  false><<<NN / RPB, 256>>>(buf0, buf1, nullptr);  // y2 + s2
    spmm_kernel<false, true ><<<NN / RPB, 256>>>(buf1, out,  b2);       // out
}

// round 10
// speedup vs baseline: 1.3850x; 1.1839x over previous
#include <cuda_runtime.h>

// MaskedCommonWeightSimpleLinearGNN — single persistent kernel.
//   w = LW * A (binary ~1% mask), same w all 3 layers.
//   out = (w^3 x) M + (w^2 1) c0^T + (w 1) c1^T + 1 b2^T
// Each of 512 blocks owns 16 rows: builds their ELL into SMEM (never leaves
// the block), runs layer1, grid-barrier, layer2 (+s2), grid-barrier, layer3
// with fused M/rank-1 epilogue. Blocks 0..64 also compute M/c0/c1 (prep)
// during the build phase. Co-residency: 35.9KB smem (6/SM) and
// __launch_bounds__(256,4) (>=4/SM) -> >=592 resident >= 512 blocks.

#define NN   8192
#define DD   64
#define CAP  160      // Binomial(8192,0.01): mean 82, sigma 9 -> mean+8.7sigma
#define RPB  16
#define PRIV 20       // per-lane slots; Binomial(256,0.01) mean 2.56 -> +11sigma
#define GRID (NN / RPB)   // 512

// ---- allocation-free scratch ----
__device__ __align__(16) float g_s1[NN];
__device__ __align__(16) float g_s2[NN];
__device__ __align__(16) float g_M[DD * DD];
__device__ __align__(16) float g_c0[DD];
__device__ __align__(16) float g_c1[DD];
__device__ __align__(16) float g_buf0[(size_t)NN * DD];
__device__ __align__(16) float g_buf1[(size_t)NN * DD];
__device__ unsigned g_count = 0;
__device__ unsigned g_gen   = 0;

// generation-based grid barrier (replay-safe: count self-resets, gen monotonic)
__device__ __forceinline__ void grid_barrier() {
    __threadfence();
    __syncthreads();
    if (threadIdx.x == 0) {
        unsigned gen = *(volatile unsigned*)&g_gen;
        unsigned t = atomicAdd(&g_count, 1);
        if (t == GRID - 1) {
            g_count = 0;
            __threadfence();
            atomicAdd(&g_gen, 1);
        } else {
            while (*(volatile unsigned*)&g_gen == gen) __nanosleep(64);
        }
    }
    __syncthreads();
    __threadfence();
}

// SpMM of one row from SMEM ELL: y = sum_k v_k * xin[c_k, l*4 .. l*4+3]
__device__ __forceinline__ float4 spmm_row(const float4* __restrict__ x4,
                                           const unsigned short* cr,
                                           const float* vr, int cnt, int l) {
    float4 a0 = make_float4(0.f,0.f,0.f,0.f), a1 = a0, a2 = a0, a3 = a0;
    int k = 0;
    for (; k + 8 <= cnt; k += 8) {
        int   c0 = cr[k],   c1 = cr[k+1], c2 = cr[k+2], c3 = cr[k+3];
        int   c4 = cr[k+4], c5 = cr[k+5], c6 = cr[k+6], c7 = cr[k+7];
        float v0 = vr[k],   v1 = vr[k+1], v2 = vr[k+2], v3 = vr[k+3];
        float v4 = vr[k+4], v5 = vr[k+5], v6 = vr[k+6], v7 = vr[k+7];
        float4 g0 = __ldg(&x4[c0 * 16 + l]);
        float4 g1 = __ldg(&x4[c1 * 16 + l]);
        float4 g2 = __ldg(&x4[c2 * 16 + l]);
        float4 g3 = __ldg(&x4[c3 * 16 + l]);
        float4 g4 = __ldg(&x4[c4 * 16 + l]);
        float4 g5 = __ldg(&x4[c5 * 16 + l]);
        float4 g6 = __ldg(&x4[c6 * 16 + l]);
        float4 g7 = __ldg(&x4[c7 * 16 + l]);
        a0.x += v0*g0.x; a0.y += v0*g0.y; a0.z += v0*g0.z; a0.w += v0*g0.w;
        a1.x += v1*g1.x; a1.y += v1*g1.y; a1.z += v1*g1.z; a1.w += v1*g1.w;
        a2.x += v2*g2.x; a2.y += v2*g2.y; a2.z += v2*g2.z; a2.w += v2*g2.w;
        a3.x += v3*g3.x; a3.y += v3*g3.y; a3.z += v3*g3.z; a3.w += v3*g3.w;
        a0.x += v4*g4.x; a0.y += v4*g4.y; a0.z += v4*g4.z; a0.w += v4*g4.w;
        a1.x += v5*g5.x; a1.y += v5*g5.y; a1.z += v5*g5.z; a1.w += v5*g5.w;
        a2.x += v6*g6.x; a2.y += v6*g6.y; a2.z += v6*g6.z; a2.w += v6*g6.w;
        a3.x += v7*g7.x; a3.y += v7*g7.y; a3.z += v7*g7.z; a3.w += v7*g7.w;
    }
    for (; k < cnt; ++k) {
        int c = cr[k]; float v = vr[k];
        float4 g = __ldg(&x4[c * 16 + l]);
        a0.x += v*g.x; a0.y += v*g.y; a0.z += v*g.z; a0.w += v*g.w;
    }
    float4 y;
    y.x = (a0.x + a1.x) + (a2.x + a3.x);
    y.y = (a0.y + a1.y) + (a2.y + a3.y);
    y.z = (a0.z + a1.z) + (a2.z + a3.z);
    y.w = (a0.w + a1.w) + (a2.w + a3.w);
    return y;
}

__global__ void __launch_bounds__(256, 4)
mega_kernel(const float* __restrict__ A,  const float* __restrict__ LW,
            const float* __restrict__ x,
            const float* __restrict__ W0, const float* __restrict__ b0,
            const float* __restrict__ W1, const float* __restrict__ b1,
            const float* __restrict__ W2, const float* __restrict__ b2,
            float* __restrict__ out) {
    __shared__ unsigned short sC[RPB * CAP];          // 5 KB  (block's ELL cols)
    __shared__ float          sV[RPB * CAP];          // 10 KB (block's ELL vals)
    __shared__ int            sCnt[RPB];
    __shared__ float          shY[RPB][DD];           // 4 KB
    __shared__ __align__(16) char uBuf[DD * DD * 4];  // 16 KB union: priv | prep scratch | sM

    int tid  = threadIdx.x;
    int wid  = tid >> 5;
    int lane = tid & 31;

    // ---------------- phase 1: build 16 rows (2 per warp) into SMEM --------
    {
        unsigned short (*priv)[32] =
            (unsigned short (*)[32])((unsigned short*)uBuf + wid * PRIV * 32);

        for (int rr = 0; rr < 2; ++rr) {
            int lr  = wid * 2 + rr;
            int row = blockIdx.x * RPB + lr;
            const float4* a4 = reinterpret_cast<const float4*>(A + (size_t)row * NN);

            // wide-prefetch scan: 512 cols/iter, 4 float4 in flight per lane
            int myc = 0;
            float4 c0 = __ldcs(&a4[lane]);
            float4 c1 = __ldcs(&a4[32 + lane]);
            float4 c2 = __ldcs(&a4[64 + lane]);
            float4 c3 = __ldcs(&a4[96 + lane]);
            #pragma unroll 1
            for (int it = 0; it < NN / 512; ++it) {
                float4 n0, n1, n2, n3;
                if (it + 1 < NN / 512) {
                    int nb = (it + 1) * 128;
                    n0 = __ldcs(&a4[nb + lane]);
                    n1 = __ldcs(&a4[nb + 32 + lane]);
                    n2 = __ldcs(&a4[nb + 64 + lane]);
                    n3 = __ldcs(&a4[nb + 96 + lane]);
                }
                int b0c = it * 512 + lane * 4;
                if (c0.x != 0.0f) { if (myc < PRIV) priv[myc][lane] = (unsigned short)(b0c    ); ++myc; }
                if (c0.y != 0.0f) { if (myc < PRIV) priv[myc][lane] = (unsigned short)(b0c + 1); ++myc; }
                if (c0.z != 0.0f) { if (myc < PRIV) priv[myc][lane] = (unsigned short)(b0c + 2); ++myc; }
                if (c0.w != 0.0f) { if (myc < PRIV) priv[myc][lane] = (unsigned short)(b0c + 3); ++myc; }
                int b1c = b0c + 128;
                if (c1.x != 0.0f) { if (myc < PRIV) priv[myc][lane] = (unsigned short)(b1c    ); ++myc; }
                if (c1.y != 0.0f) { if (myc < PRIV) priv[myc][lane] = (unsigned short)(b1c + 1); ++myc; }
                if (c1.z != 0.0f) { if (myc < PRIV) priv[myc][lane] = (unsigned short)(b1c + 2); ++myc; }
                if (c1.w != 0.0f) { if (myc < PRIV) priv[myc][lane] = (unsigned short)(b1c + 3); ++myc; }
                int b2c = b0c + 256;
                if (c2.x != 0.0f) { if (myc < PRIV) priv[myc][lane] = (unsigned short)(b2c    ); ++myc; }
                if (c2.y != 0.0f) { if (myc < PRIV) priv[myc][lane] = (unsigned short)(b2c + 1); ++myc; }
                if (c2.z != 0.0f) { if (myc < PRIV) priv[myc][lane] = (unsigned short)(b2c + 2); ++myc; }
                if (c2.w != 0.0f) { if (myc < PRIV) priv[myc][lane] = (unsigned short)(b2c + 3); ++myc; }
                int b3c = b0c + 384;
                if (c3.x != 0.0f) { if (myc < PRIV) priv[myc][lane] = (unsigned short)(b3c    ); ++myc; }
                if (c3.y != 0.0f) { if (myc < PRIV) priv[myc][lane] = (unsigned short)(b3c + 1); ++myc; }
                if (c3.z != 0.0f) { if (myc < PRIV) priv[myc][lane] = (unsigned short)(b3c + 2); ++myc; }
                if (c3.w != 0.0f) { if (myc < PRIV) priv[myc][lane] = (unsigned short)(b3c + 3); ++myc; }
                c0 = n0; c1 = n1; c2 = n2; c3 = n3;
            }
            if (myc > PRIV) myc = PRIV;

            // warp-scan compaction into sC (order-free: fp32 reorder ~1e-7 << tol)
            int inc = myc;
            #pragma unroll
            for (int o = 1; o < 32; o <<= 1) {
                int t = __shfl_up_sync(0xffffffffu, inc, o);
                if (lane >= o) inc += t;
            }
            int base = inc - myc;
            int cnt  = __shfl_sync(0xffffffffu, inc, 31);
            if (cnt > CAP) cnt = CAP;
            unsigned short* wc = sC + lr * CAP;
            for (int j = 0; j < myc; ++j) {
                int p = base + j;
                if (p < CAP) wc[p] = priv[j][lane];
            }
            __syncwarp();

            // gather LW -> sV, row sum -> g_s1
            const float* lw = LW + (size_t)row * NN;
            float* wv = sV + lr * CAP;
            float s = 0.0f;
            #pragma unroll
            for (int j = 0; j < CAP / 32; ++j) {
                int k = j * 32 + lane;
                if (k < cnt) {
                    unsigned short c = wc[k];
                    float v = __ldcs(&lw[c]);
                    wv[k] = v;
                    s += v;
                }
            }
            #pragma unroll
            for (int o = 16; o; o >>= 1) s += __shfl_xor_sync(0xffffffffu, s, o);
            if (lane == 0) {
                sCnt[lr]  = cnt;
                g_s1[row] = s;
            }
        }
    }
    __syncthreads();   // priv dead; sC/sV/sCnt complete

    // ---------------- phase 1b: prep on blocks 0..64 (overlaps other blocks) -
    if (blockIdx.x < 64) {
        float* scr = (float*)uBuf;          // reuse (priv dead)
        int d = blockIdx.x;
        int e = tid & 63, q = tid >> 6;
        // P[d,e] = sum_f W0[f,d] W1[e,f]  (4-way split over f)
        float p = 0.0f;
        #pragma unroll
        for (int j = 0; j < 16; ++j) {
            int f = q * 16 + j;
            p += __ldg(&W0[f * DD + d]) * __ldg(&W1[e * DD + f]);
        }
        scr[q * DD + e] = p;
        __syncthreads();
        float pe = 0.0f;
        if (tid < DD) pe = scr[tid] + scr[DD + tid] + scr[2 * DD + tid] + scr[3 * DD + tid];
        __syncthreads();
        if (tid < DD) scr[tid] = pe;        // P[d,:]
        __syncthreads();
        // M[d,t] = sum_e P[d,e] W2[t,e]
        float m = 0.0f;
        #pragma unroll
        for (int j = 0; j < 16; ++j) {
            int ee = q * 16 + j;
            m += scr[ee] * __ldg(&W2[e * DD + ee]);
        }
        scr[DD + q * DD + e] = m;
        __syncthreads();
        if (tid < DD)
            g_M[d * DD + tid] = scr[DD + tid] + scr[2 * DD + tid] +
                                scr[3 * DD + tid] + scr[4 * DD + tid];
    } else if (blockIdx.x == 64) {
        float* scr = (float*)uBuf;
        int t = tid & 63, q = tid >> 6;
        float s = 0.0f, s1p = 0.0f;
        #pragma unroll
        for (int j = 0; j < 16; ++j) {
            int f = q * 16 + j;
            s   += __ldg(&W1[t * DD + f]) * __ldg(&b0[f]);   // q = W1 b0
            s1p += __ldg(&W2[t * DD + f]) * __ldg(&b1[f]);   // c1 = W2 b1
        }
        scr[q * DD + t]       = s;
        scr[256 + q * DD + t] = s1p;
        __syncthreads();
        if (tid < DD) {
            g_c1[tid] = scr[256 + tid] + scr[320 + tid] + scr[384 + tid] + scr[448 + tid];
            scr[512 + tid] = scr[tid] + scr[64 + tid] + scr[128 + tid] + scr[192 + tid]; // q
        }
        __syncthreads();
        float c0p = 0.0f;
        #pragma unroll
        for (int j = 0; j < 16; ++j) {
            int ee = q * 16 + j;
            c0p += __ldg(&W2[t * DD + ee]) * scr[512 + ee];  // c0 = W2 q
        }
        __syncthreads();
        scr[q * DD + t] = c0p;
        __syncthreads();
        if (tid < DD) g_c0[tid] = scr[tid] + scr[64 + tid] + scr[128 + tid] + scr[192 + tid];
    }

    // ---------------- layer 1: y1 = w x (own rows, no cross-block dep) ------
    int r = tid >> 4, l = tid & 15;
    int row = blockIdx.x * RPB + r;
    int cnt = sCnt[r];
    const unsigned short* cr = sC + r * CAP;
    const float*          vr = sV + r * CAP;

    float4 y = spmm_row(reinterpret_cast<const float4*>(x), cr, vr, cnt, l);
    reinterpret_cast<float4*>(g_buf0)[(size_t)row * 16 + l] = y;

    grid_barrier();   // buf0 + s1 + M/c0/c1 complete chip-wide

    // stage M into uBuf (priv/prep scratch dead; synced before use in layer 3)
    {
        float4* sM4 = reinterpret_cast<float4*>(uBuf);
        const float4* gm4 = reinterpret_cast<const float4*>(g_M);
        #pragma unroll
        for (int j = 0; j < 4; ++j) sM4[j * 256 + tid] = gm4[j * 256 + tid];
    }

    // ---------------- layer 2: y2 = w y1, s2 = w s1 --------------------------
    y = spmm_row(reinterpret_cast<const float4*>(g_buf0), cr, vr, cnt, l);
    reinterpret_cast<float4*>(g_buf1)[(size_t)row * 16 + l] = y;

    {
        float s2a = 0.0f;
        for (int kk = l; kk < cnt; kk += 16)
            s2a += vr[kk] * __ldg(&g_s1[cr[kk]]);
        #pragma unroll
        for (int o = 8; o; o >>= 1) s2a += __shfl_xor_sync(0xffffffffu, s2a, o);
        if (l == 0) g_s2[row] = s2a;
    }

    grid_barrier();   // buf1 + s2 complete chip-wide

    // ---------------- layer 3: out = (w y2) M + s2 c0^T + s1 c1^T + b2 ------
    y = spmm_row(reinterpret_cast<const float4*>(g_buf1), cr, vr, cnt, l);
    reinterpret_cast<float4*>(&shY[r][0])[l] = y;
    __syncthreads();

    const float* sM = (const float*)uBuf;
    float s1v = g_s1[row], s2v = g_s2[row];
    float4 c0v = __ldg(&reinterpret_cast<const float4*>(g_c0)[l]);
    float4 c1v = __ldg(&reinterpret_cast<const float4*>(g_c1)[l]);
    float4 bv  = __ldg(&reinterpret_cast<const float4*>(b2)[l]);

    float4 acc;
    acc.x = s2v * c0v.x + s1v * c1v.x + bv.x;
    acc.y = s2v * c0v.y + s1v * c1v.y + bv.y;
    acc.z = s2v * c0v.z + s1v * c1v.z + bv.z;
    acc.w = s2v * c0v.w + s1v * c1v.w + bv.w;

    #pragma unroll 8
    for (int d = 0; d < DD; ++d) {
        float yd  = shY[r][d];
        float4 m4 = reinterpret_cast<const float4*>(sM + d * DD)[l];
        acc.x += yd * m4.x; acc.y += yd * m4.y;
        acc.z += yd * m4.z; acc.w += yd * m4.w;
    }
    reinterpret_cast<float4*>(out)[(size_t)row * 16 + l] = acc;
}

// ============================================================================
// Launch (1 kernel)
// ============================================================================
extern "C" void kernel_launch(void* const* d_in, const int* in_sizes, int n_in,
                              void* d_out, int out_size) {
    const float* x  = (const float*)d_in[0];
    const float* A  = (const float*)d_in[1];
    const float* LW = (const float*)d_in[2];
    const float* W0 = (const float*)d_in[3];
    const float* b0 = (const float*)d_in[4];
    const float* W1 = (const float*)d_in[5];
    const float* b1 = (const float*)d_in[6];
    const float* W2 = (const float*)d_in[7];
    const float* b2 = (const float*)d_in[8];

    mega_kernel<<<GRID, 256>>>(A, LW, x, W0, b0, W1, b1, W2, b2, (float*)d_out);
}

// round 12
// speedup vs baseline: 1.4738x; 1.0641x over previous
#include <cuda_runtime.h>

// MaskedCommonWeightSimpleLinearGNN — single persistent kernel, balanced grid.
//   w = LW * A (binary ~1% mask), same w all 3 layers.
//   out = (w^3 x) M + (w^2 1) c0^T + (w 1) c1^T + 1 b2^T
// 592 blocks = 4 per SM exactly (148 SMs) -> grid barriers wait on a
// perfectly balanced wave. Blocks 0..495 own 14 rows, 496..591 own 13
// (496*14 + 96*13 = 8192). ELL lives in SMEM for the whole kernel.
// R12 fix: explicit __align__(16) on every shared array that is float4-cast
// (R11 trapped: shY landed 8-aligned after the layout change).

#define NN    8192
#define DD    64
#define CAP   160     // Binomial(8192,0.01): mean 82, sigma 9 -> mean+8.7sigma
#define RPBX  14      // max rows per block
#define PRIV  20      // per-lane slots; Binomial(256,0.01) mean 2.56 -> +11sigma
#define GRID  592     // 4 * 148
#define NFULL 496     // blocks with 14 rows; rest have 13

// ---- allocation-free scratch ----
__device__ __align__(16) float g_s1[NN];
__device__ __align__(16) float g_s2[NN];
__device__ __align__(16) float g_M[DD * DD];
__device__ __align__(16) float g_c0[DD];
__device__ __align__(16) float g_c1[DD];
__device__ __align__(16) float g_buf0[(size_t)NN * DD];
__device__ __align__(16) float g_buf1[(size_t)NN * DD];
__device__ unsigned g_count = 0;
__device__ unsigned g_gen   = 0;

// generation-based grid barrier (replay-safe: count self-resets, gen monotonic)
__device__ __forceinline__ void grid_barrier() {
    __threadfence();
    __syncthreads();
    if (threadIdx.x == 0) {
        unsigned gen = *(volatile unsigned*)&g_gen;
        unsigned t = atomicAdd(&g_count, 1);
        if (t == GRID - 1) {
            g_count = 0;
            __threadfence();
            atomicAdd(&g_gen, 1);
        } else {
            while (*(volatile unsigned*)&g_gen == gen) __nanosleep(64);
        }
    }
    __syncthreads();
    __threadfence();
}

// SpMM of one row from SMEM ELL: y = sum_k v_k * xin[c_k, l*4 .. l*4+3]
__device__ __forceinline__ float4 spmm_row(const float4* __restrict__ x4,
                                           const unsigned short* cr,
                                           const float* vr, int cnt, int l) {
    float4 a0 = make_float4(0.f,0.f,0.f,0.f), a1 = a0, a2 = a0, a3 = a0;
    int k = 0;
    for (; k + 8 <= cnt; k += 8) {
        int   c0 = cr[k],   c1 = cr[k+1], c2 = cr[k+2], c3 = cr[k+3];
        int   c4 = cr[k+4], c5 = cr[k+5], c6 = cr[k+6], c7 = cr[k+7];
        float v0 = vr[k],   v1 = vr[k+1], v2 = vr[k+2], v3 = vr[k+3];
        float v4 = vr[k+4], v5 = vr[k+5], v6 = vr[k+6], v7 = vr[k+7];
        float4 g0 = __ldg(&x4[c0 * 16 + l]);
        float4 g1 = __ldg(&x4[c1 * 16 + l]);
        float4 g2 = __ldg(&x4[c2 * 16 + l]);
        float4 g3 = __ldg(&x4[c3 * 16 + l]);
        float4 g4 = __ldg(&x4[c4 * 16 + l]);
        float4 g5 = __ldg(&x4[c5 * 16 + l]);
        float4 g6 = __ldg(&x4[c6 * 16 + l]);
        float4 g7 = __ldg(&x4[c7 * 16 + l]);
        a0.x += v0*g0.x; a0.y += v0*g0.y; a0.z += v0*g0.z; a0.w += v0*g0.w;
        a1.x += v1*g1.x; a1.y += v1*g1.y; a1.z += v1*g1.z; a1.w += v1*g1.w;
        a2.x += v2*g2.x; a2.y += v2*g2.y; a2.z += v2*g2.z; a2.w += v2*g2.w;
        a3.x += v3*g3.x; a3.y += v3*g3.y; a3.z += v3*g3.z; a3.w += v3*g3.w;
        a0.x += v4*g4.x; a0.y += v4*g4.y; a0.z += v4*g4.z; a0.w += v4*g4.w;
        a1.x += v5*g5.x; a1.y += v5*g5.y; a1.z += v5*g5.z; a1.w += v5*g5.w;
        a2.x += v6*g6.x; a2.y += v6*g6.y; a2.z += v6*g6.z; a2.w += v6*g6.w;
        a3.x += v7*g7.x; a3.y += v7*g7.y; a3.z += v7*g7.z; a3.w += v7*g7.w;
    }
    for (; k < cnt; ++k) {
        int c = cr[k]; float v = vr[k];
        float4 g = __ldg(&x4[c * 16 + l]);
        a0.x += v*g.x; a0.y += v*g.y; a0.z += v*g.z; a0.w += v*g.w;
    }
    float4 y;
    y.x = (a0.x + a1.x) + (a2.x + a3.x);
    y.y = (a0.y + a1.y) + (a2.y + a3.y);
    y.z = (a0.z + a1.z) + (a2.z + a3.z);
    y.w = (a0.w + a1.w) + (a2.w + a3.w);
    return y;
}

__global__ void __launch_bounds__(256, 4)
mega_kernel(const float* __restrict__ A,  const float* __restrict__ LW,
            const float* __restrict__ x,
            const float* __restrict__ W0, const float* __restrict__ b0,
            const float* __restrict__ W1, const float* __restrict__ b1,
            const float* __restrict__ W2, const float* __restrict__ b2,
            float* __restrict__ out) {
    __shared__ __align__(16) unsigned short sC[RPBX * CAP];   // 4.4 KB
    __shared__ __align__(16) float          sV[RPBX * CAP];   // 8.75 KB
    __shared__ __align__(16) int            sCnt[16];
    __shared__ __align__(16) float          shY[RPBX][DD];    // 3.5 KB
    __shared__ __align__(16) char uBuf[DD * DD * 4];          // 16 KB union

    int tid  = threadIdx.x;
    int wid  = tid >> 5;
    int lane = tid & 31;
    int bid  = blockIdx.x;

    // row range for this block: first NFULL blocks own 14 rows, rest 13
    int row0  = (bid < NFULL) ? bid * 14 : NFULL * 14 + (bid - NFULL) * 13;
    int nrows = (bid < NFULL) ? 14 : 13;

    // ---------------- phase 1: build nrows rows into SMEM -------------------
    {
        unsigned short (*priv)[32] =
            (unsigned short (*)[32])((unsigned short*)uBuf + wid * PRIV * 32);

        for (int lr = wid; lr < nrows; lr += 8) {
            int row = row0 + lr;
            const float4* a4 = reinterpret_cast<const float4*>(A + (size_t)row * NN);

            // wide-prefetch scan: 512 cols/iter, 4 float4 in flight per lane
            int myc = 0;
            float4 c0 = __ldcs(&a4[lane]);
            float4 c1 = __ldcs(&a4[32 + lane]);
            float4 c2 = __ldcs(&a4[64 + lane]);
            float4 c3 = __ldcs(&a4[96 + lane]);
            #pragma unroll 1
            for (int it = 0; it < NN / 512; ++it) {
                float4 n0, n1, n2, n3;
                if (it + 1 < NN / 512) {
                    int nb = (it + 1) * 128;
                    n0 = __ldcs(&a4[nb + lane]);
                    n1 = __ldcs(&a4[nb + 32 + lane]);
                    n2 = __ldcs(&a4[nb + 64 + lane]);
                    n3 = __ldcs(&a4[nb + 96 + lane]);
                }
                int b0c = it * 512 + lane * 4;
                if (c0.x != 0.0f) { if (myc < PRIV) priv[myc][lane] = (unsigned short)(b0c    ); ++myc; }
                if (c0.y != 0.0f) { if (myc < PRIV) priv[myc][lane] = (unsigned short)(b0c + 1); ++myc; }
                if (c0.z != 0.0f) { if (myc < PRIV) priv[myc][lane] = (unsigned short)(b0c + 2); ++myc; }
                if (c0.w != 0.0f) { if (myc < PRIV) priv[myc][lane] = (unsigned short)(b0c + 3); ++myc; }
                int b1c = b0c + 128;
                if (c1.x != 0.0f) { if (myc < PRIV) priv[myc][lane] = (unsigned short)(b1c    ); ++myc; }
                if (c1.y != 0.0f) { if (myc < PRIV) priv[myc][lane] = (unsigned short)(b1c + 1); ++myc; }
                if (c1.z != 0.0f) { if (myc < PRIV) priv[myc][lane] = (unsigned short)(b1c + 2); ++myc; }
                if (c1.w != 0.0f) { if (myc < PRIV) priv[myc][lane] = (unsigned short)(b1c + 3); ++myc; }
                int b2c = b0c + 256;
                if (c2.x != 0.0f) { if (myc < PRIV) priv[myc][lane] = (unsigned short)(b2c    ); ++myc; }
                if (c2.y != 0.0f) { if (myc < PRIV) priv[myc][lane] = (unsigned short)(b2c + 1); ++myc; }
                if (c2.z != 0.0f) { if (myc < PRIV) priv[myc][lane] = (unsigned short)(b2c + 2); ++myc; }
                if (c2.w != 0.0f) { if (myc < PRIV) priv[myc][lane] = (unsigned short)(b2c + 3); ++myc; }
                int b3c = b0c + 384;
                if (c3.x != 0.0f) { if (myc < PRIV) priv[myc][lane] = (unsigned short)(b3c    ); ++myc; }
                if (c3.y != 0.0f) { if (myc < PRIV) priv[myc][lane] = (unsigned short)(b3c + 1); ++myc; }
                if (c3.z != 0.0f) { if (myc < PRIV) priv[myc][lane] = (unsigned short)(b3c + 2); ++myc; }
                if (c3.w != 0.0f) { if (myc < PRIV) priv[myc][lane] = (unsigned short)(b3c + 3); ++myc; }
                c0 = n0; c1 = n1; c2 = n2; c3 = n3;
            }
            if (myc > PRIV) myc = PRIV;

            // warp-scan compaction into sC (order-free: fp32 reorder ~1e-7 << tol)
            int inc = myc;
            #pragma unroll
            for (int o = 1; o < 32; o <<= 1) {
                int t = __shfl_up_sync(0xffffffffu, inc, o);
                if (lane >= o) inc += t;
            }
            int base = inc - myc;
            int cnt  = __shfl_sync(0xffffffffu, inc, 31);
            if (cnt > CAP) cnt = CAP;
            unsigned short* wc = sC + lr * CAP;
            for (int j = 0; j < myc; ++j) {
                int p = base + j;
                if (p < CAP) wc[p] = priv[j][lane];
            }
            __syncwarp();

            // gather LW -> sV, row sum -> g_s1
            const float* lw = LW + (size_t)row * NN;
            float* wv = sV + lr * CAP;
            float s = 0.0f;
            #pragma unroll
            for (int j = 0; j < CAP / 32; ++j) {
                int k = j * 32 + lane;
                if (k < cnt) {
                    unsigned short c = wc[k];
                    float v = __ldcs(&lw[c]);
                    wv[k] = v;
                    s += v;
                }
            }
            #pragma unroll
            for (int o = 16; o; o >>= 1) s += __shfl_xor_sync(0xffffffffu, s, o);
            if (lane == 0) {
                sCnt[lr]  = cnt;
                g_s1[row] = s;
            }
        }
    }
    __syncthreads();   // priv dead; sC/sV/sCnt complete

    // ---------------- phase 1b: prep on blocks 0..64 (overlaps other blocks) -
    if (bid < 64) {
        float* scr = (float*)uBuf;          // reuse (priv dead)
        int d = bid;
        int e = tid & 63, q = tid >> 6;
        // P[d,e] = sum_f W0[f,d] W1[e,f]  (4-way split over f)
        float p = 0.0f;
        #pragma unroll
        for (int j = 0; j < 16; ++j) {
            int f = q * 16 + j;
            p += __ldg(&W0[f * DD + d]) * __ldg(&W1[e * DD + f]);
        }
        scr[q * DD + e] = p;
        __syncthreads();
        float pe = 0.0f;
        if (tid < DD) pe = scr[tid] + scr[DD + tid] + scr[2 * DD + tid] + scr[3 * DD + tid];
        __syncthreads();
        if (tid < DD) scr[tid] = pe;        // P[d,:]
        __syncthreads();
        // M[d,t] = sum_e P[d,e] W2[t,e]
        float m = 0.0f;
        #pragma unroll
        for (int j = 0; j < 16; ++j) {
            int ee = q * 16 + j;
            m += scr[ee] * __ldg(&W2[e * DD + ee]);
        }
        scr[DD + q * DD + e] = m;
        __syncthreads();
        if (tid < DD)
            g_M[d * DD + tid] = scr[DD + tid] + scr[2 * DD + tid] +
                                scr[3 * DD + tid] + scr[4 * DD + tid];
    } else if (bid == 64) {
        float* scr = (float*)uBuf;
        int t = tid & 63, q = tid >> 6;
        float s = 0.0f, s1p = 0.0f;
        #pragma unroll
        for (int j = 0; j < 16; ++j) {
            int f = q * 16 + j;
            s   += __ldg(&W1[t * DD + f]) * __ldg(&b0[f]);   // q = W1 b0
            s1p += __ldg(&W2[t * DD + f]) * __ldg(&b1[f]);   // c1 = W2 b1
        }
        scr[q * DD + t]       = s;
        scr[256 + q * DD + t] = s1p;
        __syncthreads();
        if (tid < DD) {
            g_c1[tid] = scr[256 + tid] + scr[320 + tid] + scr[384 + tid] + scr[448 + tid];
            scr[512 + tid] = scr[tid] + scr[64 + tid] + scr[128 + tid] + scr[192 + tid]; // q
        }
        __syncthreads();
        float c0p = 0.0f;
        #pragma unroll
        for (int j = 0; j < 16; ++j) {
            int ee = q * 16 + j;
            c0p += __ldg(&W2[t * DD + ee]) * scr[512 + ee];  // c0 = W2 q
        }
        __syncthreads();
        scr[q * DD + t] = c0p;
        __syncthreads();
        if (tid < DD) g_c0[tid] = scr[tid] + scr[64 + tid] + scr[128 + tid] + scr[192 + tid];
    }

    // ---------------- layer 1: y1 = w x (own rows, no cross-block dep) ------
    int r = tid >> 4, l = tid & 15;
    bool active = (r < nrows);
    int row = row0 + (active ? r : 0);
    int cnt = active ? sCnt[r] : 0;
    const unsigned short* cr = sC + (active ? r : 0) * CAP;
    const float*          vr = sV + (active ? r : 0) * CAP;

    float4 y = spmm_row(reinterpret_cast<const float4*>(x), cr, vr, cnt, l);
    if (active)
        reinterpret_cast<float4*>(g_buf0)[(size_t)row * 16 + l] = y;

    grid_barrier();   // buf0 + s1 + M/c0/c1 complete chip-wide

    // stage M into uBuf (priv/prep scratch dead; synced before use in layer 3)
    {
        float4* sM4 = reinterpret_cast<float4*>(uBuf);
        const float4* gm4 = reinterpret_cast<const float4*>(g_M);
        #pragma unroll
        for (int j = 0; j < 4; ++j) sM4[j * 256 + tid] = gm4[j * 256 + tid];
    }

    // ---------------- layer 2: y2 = w y1, s2 = w s1 --------------------------
    y = spmm_row(reinterpret_cast<const float4*>(g_buf0), cr, vr, cnt, l);
    if (active)
        reinterpret_cast<float4*>(g_buf1)[(size_t)row * 16 + l] = y;

    {
        float s2a = 0.0f;
        for (int kk = l; kk < cnt; kk += 16)
            s2a += vr[kk] * __ldg(&g_s1[cr[kk]]);
        #pragma unroll
        for (int o = 8; o; o >>= 1) s2a += __shfl_xor_sync(0xffffffffu, s2a, o);
        if (active && l == 0) g_s2[row] = s2a;
    }

    grid_barrier();   // buf1 + s2 complete chip-wide

    // ---------------- layer 3: out = (w y2) M + s2 c0^T + s1 c1^T + b2 ------
    y = spmm_row(reinterpret_cast<const float4*>(g_buf1), cr, vr, cnt, l);
    if (active)
        reinterpret_cast<float4*>(&shY[r][0])[l] = y;
    __syncthreads();

    if (active) {
        const float* sM = (const float*)uBuf;
        float s1v = g_s1[row], s2v = g_s2[row];
        float4 c0v = __ldg(&reinterpret_cast<const float4*>(g_c0)[l]);
        float4 c1v = __ldg(&reinterpret_cast<const float4*>(g_c1)[l]);
        float4 bv  = __ldg(&reinterpret_cast<const float4*>(b2)[l]);

        float4 acc;
        acc.x = s2v * c0v.x + s1v * c1v.x + bv.x;
        acc.y = s2v * c0v.y + s1v * c1v.y + bv.y;
        acc.z = s2v * c0v.z + s1v * c1v.z + bv.z;
        acc.w = s2v * c0v.w + s1v * c1v.w + bv.w;

        #pragma unroll 8
        for (int d = 0; d < DD; ++d) {
            float yd  = shY[r][d];
            float4 m4 = reinterpret_cast<const float4*>(sM + d * DD)[l];
            acc.x += yd * m4.x; acc.y += yd * m4.y;
            acc.z += yd * m4.z; acc.w += yd * m4.w;
        }
        reinterpret_cast<float4*>(out)[(size_t)row * 16 + l] = acc;
    }
}

// ============================================================================
// Launch (1 kernel)
// ============================================================================
extern "C" void kernel_launch(void* const* d_in, const int* in_sizes, int n_in,
                              void* d_out, int out_size) {
    const float* x  = (const float*)d_in[0];
    const float* A  = (const float*)d_in[1];
    const float* LW = (const float*)d_in[2];
    const float* W0 = (const float*)d_in[3];
    const float* b0 = (const float*)d_in[4];
    const float* W1 = (const float*)d_in[5];
    const float* b1 = (const float*)d_in[6];
    const float* W2 = (const float*)d_in[7];
    const float* b2 = (const float*)d_in[8];

    mega_kernel<<<GRID, 256>>>(A, LW, x, W0, b0, W1, b1, W2, b2, (float*)d_out);
}

// round 13
// speedup vs baseline: 1.4956x; 1.0148x over previous
#include <cuda_runtime.h>
#include <cuda_fp16.h>

// MaskedCommonWeightSimpleLinearGNN — single persistent kernel, balanced grid,
// fp16 intermediate buffers (layers 2/3 are L2-BW-capped: halving the row
// footprint 256B->128B halves their time; accumulation stays fp32, only two
// storage roundings ~5e-4 << 1e-3 tol).
//   out = (w^3 x) M + (w^2 1) c0^T + (w 1) c1^T + 1 b2^T
// 592 blocks = 4/SM exactly. Blocks 0..495 own 14 rows, rest 13.

#define NN    8192
#define DD    64
#define CAP   160     // Binomial(8192,0.01): mean 82, sigma 9 -> mean+8.7sigma
#define RPBX  14
#define PRIV  20      // per-lane slots; Binomial(256,0.01) mean 2.56 -> +11sigma
#define GRID  592     // 4 * 148
#define NFULL 496     // blocks with 14 rows; rest have 13

// ---- allocation-free scratch ----
__device__ __align__(16) float  g_s1[NN];
__device__ __align__(16) float  g_s2[NN];
__device__ __align__(16) float  g_M[DD * DD];
__device__ __align__(16) float  g_c0[DD];
__device__ __align__(16) float  g_c1[DD];
__device__ __align__(16) __half g_buf0[(size_t)NN * DD];   // 1 MB
__device__ __align__(16) __half g_buf1[(size_t)NN * DD];   // 1 MB
__device__ unsigned g_count = 0;
__device__ unsigned g_gen   = 0;

// generation-based grid barrier (replay-safe: count self-resets, gen monotonic)
__device__ __forceinline__ void grid_barrier() {
    __threadfence();
    __syncthreads();
    if (threadIdx.x == 0) {
        unsigned gen = *(volatile unsigned*)&g_gen;
        unsigned t = atomicAdd(&g_count, 1);
        if (t == GRID - 1) {
            g_count = 0;
            __threadfence();
            atomicAdd(&g_gen, 1);
        } else {
            while (*(volatile unsigned*)&g_gen == gen) __nanosleep(64);
        }
    }
    __syncthreads();
    __threadfence();
}

// fp32 gather SpMM (layer 1: x input is fp32; 256B/row)
__device__ __forceinline__ float4 spmm_row_f32(const float4* __restrict__ x4,
                                               const unsigned short* cr,
                                               const float* vr, int cnt, int l) {
    float4 a0 = make_float4(0.f,0.f,0.f,0.f), a1 = a0, a2 = a0, a3 = a0;
    int k = 0;
    for (; k + 8 <= cnt; k += 8) {
        int   c0 = cr[k],   c1 = cr[k+1], c2 = cr[k+2], c3 = cr[k+3];
        int   c4 = cr[k+4], c5 = cr[k+5], c6 = cr[k+6], c7 = cr[k+7];
        float v0 = vr[k],   v1 = vr[k+1], v2 = vr[k+2], v3 = vr[k+3];
        float v4 = vr[k+4], v5 = vr[k+5], v6 = vr[k+6], v7 = vr[k+7];
        float4 g0 = __ldg(&x4[c0 * 16 + l]);
        float4 g1 = __ldg(&x4[c1 * 16 + l]);
        float4 g2 = __ldg(&x4[c2 * 16 + l]);
        float4 g3 = __ldg(&x4[c3 * 16 + l]);
        float4 g4 = __ldg(&x4[c4 * 16 + l]);
        float4 g5 = __ldg(&x4[c5 * 16 + l]);
        float4 g6 = __ldg(&x4[c6 * 16 + l]);
        float4 g7 = __ldg(&x4[c7 * 16 + l]);
        a0.x += v0*g0.x; a0.y += v0*g0.y; a0.z += v0*g0.z; a0.w += v0*g0.w;
        a1.x += v1*g1.x; a1.y += v1*g1.y; a1.z += v1*g1.z; a1.w += v1*g1.w;
        a2.x += v2*g2.x; a2.y += v2*g2.y; a2.z += v2*g2.z; a2.w += v2*g2.w;
        a3.x += v3*g3.x; a3.y += v3*g3.y; a3.z += v3*g3.z; a3.w += v3*g3.w;
        a0.x += v4*g4.x; a0.y += v4*g4.y; a0.z += v4*g4.z; a0.w += v4*g4.w;
        a1.x += v5*g5.x; a1.y += v5*g5.y; a1.z += v5*g5.z; a1.w += v5*g5.w;
        a2.x += v6*g6.x; a2.y += v6*g6.y; a2.z += v6*g6.z; a2.w += v6*g6.w;
        a3.x += v7*g7.x; a3.y += v7*g7.y; a3.z += v7*g7.z; a3.w += v7*g7.w;
    }
    for (; k < cnt; ++k) {
        int c = cr[k]; float v = vr[k];
        float4 g = __ldg(&x4[c * 16 + l]);
        a0.x += v*g.x; a0.y += v*g.y; a0.z += v*g.z; a0.w += v*g.w;
    }
    float4 y;
    y.x = (a0.x + a1.x) + (a2.x + a3.x);
    y.y = (a0.y + a1.y) + (a2.y + a3.y);
    y.z = (a0.z + a1.z) + (a2.z + a3.z);
    y.w = (a0.w + a1.w) + (a2.w + a3.w);
    return y;
}

// fp16 gather SpMM (layers 2/3: 128B/row, fp32 accumulation)
__device__ __forceinline__ float4 spmm_row_f16(const uint2* __restrict__ xh,
                                               const unsigned short* cr,
                                               const float* vr, int cnt, int l) {
    float4 a0 = make_float4(0.f,0.f,0.f,0.f), a1 = a0, a2 = a0, a3 = a0;
    int k = 0;
    for (; k + 8 <= cnt; k += 8) {
        int   c0 = cr[k],   c1 = cr[k+1], c2 = cr[k+2], c3 = cr[k+3];
        int   c4 = cr[k+4], c5 = cr[k+5], c6 = cr[k+6], c7 = cr[k+7];
        float v0 = vr[k],   v1 = vr[k+1], v2 = vr[k+2], v3 = vr[k+3];
        float v4 = vr[k+4], v5 = vr[k+5], v6 = vr[k+6], v7 = vr[k+7];
        uint2 g0 = __ldg(&xh[c0 * 16 + l]);
        uint2 g1 = __ldg(&xh[c1 * 16 + l]);
        uint2 g2 = __ldg(&xh[c2 * 16 + l]);
        uint2 g3 = __ldg(&xh[c3 * 16 + l]);
        uint2 g4 = __ldg(&xh[c4 * 16 + l]);
        uint2 g5 = __ldg(&xh[c5 * 16 + l]);
        uint2 g6 = __ldg(&xh[c6 * 16 + l]);
        uint2 g7 = __ldg(&xh[c7 * 16 + l]);
        #define ACC_H(ar, gg, vv) { \
            float2 f0 = __half22float2(*(const __half2*)&(gg).x); \
            float2 f1 = __half22float2(*(const __half2*)&(gg).y); \
            (ar).x += (vv) * f0.x; (ar).y += (vv) * f0.y; \
            (ar).z += (vv) * f1.x; (ar).w += (vv) * f1.y; }
        ACC_H(a0, g0, v0) ACC_H(a1, g1, v1) ACC_H(a2, g2, v2) ACC_H(a3, g3, v3)
        ACC_H(a0, g4, v4) ACC_H(a1, g5, v5) ACC_H(a2, g6, v6) ACC_H(a3, g7, v7)
    }
    for (; k < cnt; ++k) {
        int c = cr[k]; float v = vr[k];
        uint2 g = __ldg(&xh[c * 16 + l]);
        ACC_H(a0, g, v)
        #undef ACC_H
    }
    float4 y;
    y.x = (a0.x + a1.x) + (a2.x + a3.x);
    y.y = (a0.y + a1.y) + (a2.y + a3.y);
    y.z = (a0.z + a1.z) + (a2.z + a3.z);
    y.w = (a0.w + a1.w) + (a2.w + a3.w);
    return y;
}

__device__ __forceinline__ uint2 pack_half4(float4 y) {
    __half2 h0 = __floats2half2_rn(y.x, y.y);
    __half2 h1 = __floats2half2_rn(y.z, y.w);
    uint2 u;
    u.x = *(unsigned*)&h0;
    u.y = *(unsigned*)&h1;
    return u;
}

__global__ void __launch_bounds__(256, 4)
mega_kernel(const float* __restrict__ A,  const float* __restrict__ LW,
            const float* __restrict__ x,
            const float* __restrict__ W0, const float* __restrict__ b0,
            const float* __restrict__ W1, const float* __restrict__ b1,
            const float* __restrict__ W2, const float* __restrict__ b2,
            float* __restrict__ out) {
    __shared__ __align__(16) unsigned short sC[RPBX * CAP];   // 4.4 KB
    __shared__ __align__(16) float          sV[RPBX * CAP];   // 8.75 KB
    __shared__ __align__(16) int            sCnt[16];
    __shared__ __align__(16) float          shY[RPBX][DD];    // 3.5 KB
    __shared__ __align__(16) char uBuf[DD * DD * 4];          // 16 KB union

    int tid  = threadIdx.x;
    int wid  = tid >> 5;
    int lane = tid & 31;
    int bid  = blockIdx.x;

    int row0  = (bid < NFULL) ? bid * 14 : NFULL * 14 + (bid - NFULL) * 13;
    int nrows = (bid < NFULL) ? 14 : 13;

    // ---------------- phase 1: build nrows rows into SMEM -------------------
    {
        unsigned short (*priv)[32] =
            (unsigned short (*)[32])((unsigned short*)uBuf + wid * PRIV * 32);

        for (int lr = wid; lr < nrows; lr += 8) {
            int row = row0 + lr;
            const float4* a4 = reinterpret_cast<const float4*>(A + (size_t)row * NN);

            int myc = 0;
            float4 c0 = __ldcs(&a4[lane]);
            float4 c1 = __ldcs(&a4[32 + lane]);
            float4 c2 = __ldcs(&a4[64 + lane]);
            float4 c3 = __ldcs(&a4[96 + lane]);
            #pragma unroll 1
            for (int it = 0; it < NN / 512; ++it) {
                float4 n0, n1, n2, n3;
                if (it + 1 < NN / 512) {
                    int nb = (it + 1) * 128;
                    n0 = __ldcs(&a4[nb + lane]);
                    n1 = __ldcs(&a4[nb + 32 + lane]);
                    n2 = __ldcs(&a4[nb + 64 + lane]);
                    n3 = __ldcs(&a4[nb + 96 + lane]);
                }
                int b0c = it * 512 + lane * 4;
                if (c0.x != 0.0f) { if (myc < PRIV) priv[myc][lane] = (unsigned short)(b0c    ); ++myc; }
                if (c0.y != 0.0f) { if (myc < PRIV) priv[myc][lane] = (unsigned short)(b0c + 1); ++myc; }
                if (c0.z != 0.0f) { if (myc < PRIV) priv[myc][lane] = (unsigned short)(b0c + 2); ++myc; }
                if (c0.w != 0.0f) { if (myc < PRIV) priv[myc][lane] = (unsigned short)(b0c + 3); ++myc; }
                int b1c = b0c + 128;
                if (c1.x != 0.0f) { if (myc < PRIV) priv[myc][lane] = (unsigned short)(b1c    ); ++myc; }
                if (c1.y != 0.0f) { if (myc < PRIV) priv[myc][lane] = (unsigned short)(b1c + 1); ++myc; }
                if (c1.z != 0.0f) { if (myc < PRIV) priv[myc][lane] = (unsigned short)(b1c + 2); ++myc; }
                if (c1.w != 0.0f) { if (myc < PRIV) priv[myc][lane] = (unsigned short)(b1c + 3); ++myc; }
                int b2c = b0c + 256;
                if (c2.x != 0.0f) { if (myc < PRIV) priv[myc][lane] = (unsigned short)(b2c    ); ++myc; }
                if (c2.y != 0.0f) { if (myc < PRIV) priv[myc][lane] = (unsigned short)(b2c + 1); ++myc; }
                if (c2.z != 0.0f) { if (myc < PRIV) priv[myc][lane] = (unsigned short)(b2c + 2); ++myc; }
                if (c2.w != 0.0f) { if (myc < PRIV) priv[myc][lane] = (unsigned short)(b2c + 3); ++myc; }
                int b3c = b0c + 384;
                if (c3.x != 0.0f) { if (myc < PRIV) priv[myc][lane] = (unsigned short)(b3c    ); ++myc; }
                if (c3.y != 0.0f) { if (myc < PRIV) priv[myc][lane] = (unsigned short)(b3c + 1); ++myc; }
                if (c3.z != 0.0f) { if (myc < PRIV) priv[myc][lane] = (unsigned short)(b3c + 2); ++myc; }
                if (c3.w != 0.0f) { if (myc < PRIV) priv[myc][lane] = (unsigned short)(b3c + 3); ++myc; }
                c0 = n0; c1 = n1; c2 = n2; c3 = n3;
            }
            if (myc > PRIV) myc = PRIV;

            int inc = myc;
            #pragma unroll
            for (int o = 1; o < 32; o <<= 1) {
                int t = __shfl_up_sync(0xffffffffu, inc, o);
                if (lane >= o) inc += t;
            }
            int base = inc - myc;
            int cnt  = __shfl_sync(0xffffffffu, inc, 31);
            if (cnt > CAP) cnt = CAP;
            unsigned short* wc = sC + lr * CAP;
            for (int j = 0; j < myc; ++j) {
                int p = base + j;
                if (p < CAP) wc[p] = priv[j][lane];
            }
            __syncwarp();

            const float* lw = LW + (size_t)row * NN;
            float* wv = sV + lr * CAP;
            float s = 0.0f;
            #pragma unroll
            for (int j = 0; j < CAP / 32; ++j) {
                int k = j * 32 + lane;
                if (k < cnt) {
                    unsigned short c = wc[k];
                    float v = __ldcs(&lw[c]);
                    wv[k] = v;
                    s += v;
                }
            }
            #pragma unroll
            for (int o = 16; o; o >>= 1) s += __shfl_xor_sync(0xffffffffu, s, o);
            if (lane == 0) {
                sCnt[lr]  = cnt;
                g_s1[row] = s;
            }
        }
    }
    __syncthreads();

    // ---------------- phase 1b: prep on blocks 0..64 -------------------------
    if (bid < 64) {
        float* scr = (float*)uBuf;
        int d = bid;
        int e = tid & 63, q = tid >> 6;
        float p = 0.0f;
        #pragma unroll
        for (int j = 0; j < 16; ++j) {
            int f = q * 16 + j;
            p += __ldg(&W0[f * DD + d]) * __ldg(&W1[e * DD + f]);
        }
        scr[q * DD + e] = p;
        __syncthreads();
        float pe = 0.0f;
        if (tid < DD) pe = scr[tid] + scr[DD + tid] + scr[2 * DD + tid] + scr[3 * DD + tid];
        __syncthreads();
        if (tid < DD) scr[tid] = pe;
        __syncthreads();
        float m = 0.0f;
        #pragma unroll
        for (int j = 0; j < 16; ++j) {
            int ee = q * 16 + j;
            m += scr[ee] * __ldg(&W2[e * DD + ee]);
        }
        scr[DD + q * DD + e] = m;
        __syncthreads();
        if (tid < DD)
            g_M[d * DD + tid] = scr[DD + tid] + scr[2 * DD + tid] +
                                scr[3 * DD + tid] + scr[4 * DD + tid];
    } else if (bid == 64) {
        float* scr = (float*)uBuf;
        int t = tid & 63, q = tid >> 6;
        float s = 0.0f, s1p = 0.0f;
        #pragma unroll
        for (int j = 0; j < 16; ++j) {
            int f = q * 16 + j;
            s   += __ldg(&W1[t * DD + f]) * __ldg(&b0[f]);
            s1p += __ldg(&W2[t * DD + f]) * __ldg(&b1[f]);
        }
        scr[q * DD + t]       = s;
        scr[256 + q * DD + t] = s1p;
        __syncthreads();
        if (tid < DD) {
            g_c1[tid] = scr[256 + tid] + scr[320 + tid] + scr[384 + tid] + scr[448 + tid];
            scr[512 + tid] = scr[tid] + scr[64 + tid] + scr[128 + tid] + scr[192 + tid];
        }
        __syncthreads();
        float c0p = 0.0f;
        #pragma unroll
        for (int j = 0; j < 16; ++j) {
            int ee = q * 16 + j;
            c0p += __ldg(&W2[t * DD + ee]) * scr[512 + ee];
        }
        __syncthreads();
        scr[q * DD + t] = c0p;
        __syncthreads();
        if (tid < DD) g_c0[tid] = scr[tid] + scr[64 + tid] + scr[128 + tid] + scr[192 + tid];
    }

    // ---------------- layer 1: y1 = w x (fp32 gathers, fp16 store) ----------
    int r = tid >> 4, l = tid & 15;
    bool active = (r < nrows);
    int row = row0 + (active ? r : 0);
    int cnt = active ? sCnt[r] : 0;
    const unsigned short* cr = sC + (active ? r : 0) * CAP;
    const float*          vr = sV + (active ? r : 0) * CAP;

    float4 y = spmm_row_f32(reinterpret_cast<const float4*>(x), cr, vr, cnt, l);
    if (active)
        reinterpret_cast<uint2*>(g_buf0)[(size_t)row * 16 + l] = pack_half4(y);

    grid_barrier();   // buf0 + s1 + M/c0/c1 complete chip-wide

    // stage M into uBuf
    {
        float4* sM4 = reinterpret_cast<float4*>(uBuf);
        const float4* gm4 = reinterpret_cast<const float4*>(g_M);
        #pragma unroll
        for (int j = 0; j < 4; ++j) sM4[j * 256 + tid] = gm4[j * 256 + tid];
    }

    // ---------------- layer 2: y2 = w y1 (fp16 gathers), s2 = w s1 ----------
    y = spmm_row_f16(reinterpret_cast<const uint2*>(g_buf0), cr, vr, cnt, l);
    if (active)
        reinterpret_cast<uint2*>(g_buf1)[(size_t)row * 16 + l] = pack_half4(y);

    {
        float s2a = 0.0f;
        for (int kk = l; kk < cnt; kk += 16)
            s2a += vr[kk] * __ldg(&g_s1[cr[kk]]);
        #pragma unroll
        for (int o = 8; o; o >>= 1) s2a += __shfl_xor_sync(0xffffffffu, s2a, o);
        if (active && l == 0) g_s2[row] = s2a;
    }

    grid_barrier();   // buf1 + s2 complete chip-wide

    // ---------------- layer 3: out = (w y2) M + s2 c0^T + s1 c1^T + b2 ------
    y = spmm_row_f16(reinterpret_cast<const uint2*>(g_buf1), cr, vr, cnt, l);
    if (active)
        reinterpret_cast<float4*>(&shY[r][0])[l] = y;
    __syncthreads();

    if (active) {
        const float* sM = (const float*)uBuf;
        float s1v = g_s1[row], s2v = g_s2[row];
        float4 c0v = __ldg(&reinterpret_cast<const float4*>(g_c0)[l]);
        float4 c1v = __ldg(&reinterpret_cast<const float4*>(g_c1)[l]);
        float4 bv  = __ldg(&reinterpret_cast<const float4*>(b2)[l]);

        float4 acc;
        acc.x = s2v * c0v.x + s1v * c1v.x + bv.x;
        acc.y = s2v * c0v.y + s1v * c1v.y + bv.y;
        acc.z = s2v * c0v.z + s1v * c1v.z + bv.z;
        acc.w = s2v * c0v.w + s1v * c1v.w + bv.w;

        #pragma unroll 8
        for (int d = 0; d < DD; ++d) {
            float yd  = shY[r][d];
            float4 m4 = reinterpret_cast<const float4*>(sM + d * DD)[l];
            acc.x += yd * m4.x; acc.y += yd * m4.y;
            acc.z += yd * m4.z; acc.w += yd * m4.w;
        }
        reinterpret_cast<float4*>(out)[(size_t)row * 16 + l] = acc;
    }
}

// ============================================================================
// Launch (1 kernel)
// ============================================================================
extern "C" void kernel_launch(void* const* d_in, const int* in_sizes, int n_in,
                              void* d_out, int out_size) {
    const float* x  = (const float*)d_in[0];
    const float* A  = (const float*)d_in[1];
    const float* LW = (const float*)d_in[2];
    const float* W0 = (const float*)d_in[3];
    const float* b0 = (const float*)d_in[4];
    const float* W1 = (const float*)d_in[5];
    const float* b1 = (const float*)d_in[6];
    const float* W2 = (const float*)d_in[7];
    const float* b2 = (const float*)d_in[8];

    mega_kernel<<<GRID, 256>>>(A, LW, x, W0, b0, W1, b1, W2, b2, (float*)d_out);
}